// round 13
// baseline (speedup 1.0000x reference)
#include <cuda_runtime.h>

#define BSZ 32
#define LP 96
#define DM 12
#define ED 768
#define NS 8
#define NL 10
#define EMB 256
#define PP 50
#define ROWS (BSZ*LP)      // 3072
#define XZW (2*ED)         // 1536
#define DBLW 17
#define DBLS 20
#define NTH 384
#define NBLK 256
#define NSEG 8
#define SEGL 12
#define PQSTRIDE ((NSEG-1)*BSZ*NS*ED)

// smem layout (floats)
#define S_XC   0
#define S_DL   (SEGL*ED)                 // 9216
#define S_DB   (2*SEGL*ED)               // 18432
#define S_TMP  (2*SEGL*ED + SEGL*DBLS)   // 18672
#define DYNF   (S_TMP + 2*SEGL*DBLW + 32)

// ---------------- scratch ----------------
__device__ __align__(16) float g_h[ROWS*DM];
__device__ __align__(16) float g_xz[ROWS*XZW];
__device__ __align__(16) float g_P[2*PQSTRIDE];
__device__ __align__(16) float g_q[2*PQSTRIDE];
__device__ __align__(16) float g_A2[NL*ED*NS];
__device__ __align__(16) float g_cwT[NL*4*ED];
__device__ float g_bns[2*DM];
__device__ unsigned g_xz_ready[NBLK];
__device__ unsigned g_xz_ack[NBLK];
__device__ unsigned g_pq_ready[NBLK];
__device__ unsigned g_pq_ack[NBLK];
__device__ volatile unsigned g_bar_gen;
__device__ unsigned g_bar_cnt;

// ---------------- fast math ----------------
__device__ __forceinline__ float ex2f_(float x){ float y; asm("ex2.approx.f32 %0, %1;":"=f"(y):"f"(x)); return y; }
__device__ __forceinline__ float lg2f_(float x){ float y; asm("lg2.approx.f32 %0, %1;":"=f"(y):"f"(x)); return y; }
__device__ __forceinline__ float rcpf_(float x){ float y; asm("rcp.approx.f32 %0, %1;":"=f"(y):"f"(x)); return y; }
#define L2E 1.4426950408889634f
#define LN2 0.6931471805599453f
__device__ __forceinline__ float sigmoidf_(float x){ return rcpf_(1.0f + ex2f_(-x*L2E)); }
__device__ __forceinline__ float siluf_(float x){ return x * sigmoidf_(x); }
__device__ __forceinline__ float softplusf_(float x){
    return (x > 20.0f) ? x : LN2*lg2f_(1.0f + ex2f_(x*L2E));
}

// ---------------- sync primitives ----------------
__device__ __forceinline__ void gridbar(){
    __threadfence();
    __syncthreads();
    if (threadIdx.x == 0){
        unsigned gen = g_bar_gen;
        unsigned old = atomicAdd(&g_bar_cnt, 1u);
        if (old == gridDim.x - 1u){
            g_bar_cnt = 0u;
            __threadfence();
            g_bar_gen = gen + 1u;
        } else {
            while (g_bar_gen == gen) __nanosleep(20);
        }
        __threadfence();
    }
    __syncthreads();
}
__device__ __forceinline__ void wait_ge(unsigned* ctr, unsigned target){
    __syncthreads();
    if (threadIdx.x == 0){
        volatile unsigned* p = (volatile unsigned*)ctr;
        unsigned v = *p;
        while ((int)(v - target) < 0){ __nanosleep(8); v = *p; }
        __threadfence();   // acquire: CCTL.IVALL flushes stale L1 for the SM
    }
    __syncthreads();
}
// proper release: ALL threads fence their stores, then barrier, then flag
__device__ __forceinline__ void signal_release(unsigned* ctr){
    __threadfence();
    __syncthreads();
    if (threadIdx.x == 0) atomicAdd(ctr, 1u);
}

// ---------------- megakernel ----------------
__global__ void __launch_bounds__(NTH,2) k_mega(
    const float* __restrict__ x,
    const float* __restrict__ conv_re_w, const float* __restrict__ conv_re_b,
    const float* __restrict__ conv_im_w, const float* __restrict__ conv_im_b,
    const float* __restrict__ pos,
    const float* __restrict__ bn_gamma, const float* __restrict__ bn_beta,
    const float* __restrict__ rms_w,
    const float* __restrict__ in_proj_w,
    const float* __restrict__ conv1d_w, const float* __restrict__ conv1d_b,
    const float* __restrict__ x_proj_w,
    const float* __restrict__ dt_proj_w, const float* __restrict__ dt_proj_b,
    const float* __restrict__ A_log,  const float* __restrict__ Dp,
    const float* __restrict__ out_proj_w,
    const float* __restrict__ fc_w, const float* __restrict__ fc_b,
    float* __restrict__ out)
{
    extern __shared__ float sm[];
    float* sxc  = sm + S_XC;
    float* sdl  = sm + S_DL;
    float* sdb  = sm + S_DB;
    float* stmp = sm + S_TMP;
    const int NB  = gridDim.x;
    const int bid = blockIdx.x;
    const int tid = threadIdx.x;
    const int gsz = NB*NTH;
    const int gtid = bid*NTH + tid;
    const int warp = tid >> 5, lane = tid & 31;

    const int seg_b = bid >> 3;            // batch
    const int seg_s = bid & 7;             // eighth
    const int rowbase = bid*SEGL;

    // ===== phase 0 =====
    if (tid == 0){
        g_xz_ready[bid]=0u; g_xz_ack[bid]=0u;
        g_pq_ready[bid]=0u; g_pq_ack[bid]=0u;
    }
    for (int i = gtid; i < NL*ED*NS; i += gsz) g_A2[i] = -expf(A_log[i]) * L2E;
    for (int i = gtid; i < NL*ED; i += gsz){
        int layer = i / ED, e = i % ED;
        const float* wp = conv1d_w + i*3;
        float* dst = g_cwT + layer*4*ED;
        dst[0*ED+e] = wp[0];
        dst[1*ED+e] = wp[1];
        dst[2*ED+e] = wp[2];
        dst[3*ED+e] = conv1d_b[i];
    }
    if (gtid < 2*DM) g_bns[gtid] = 0.f;
    for (int idx = gtid; idx < ROWS*DM; idx += gsz){
        int row = idx / DM, o = idx % DM;
        int b = row / LP, l = row % LP;
        const float* xr = x + b*(2*LP*PP) + l*PP;
        const float* xi = xr + LP*PP;
        float acc;
        if (o < 6){
            acc = conv_re_b[o] - conv_im_b[o];
            const float* w1 = conv_re_w + o*PP; const float* w2 = conv_im_w + o*PP;
            #pragma unroll 10
            for (int k=0;k<PP;k++) acc += xr[k]*w1[k] - xi[k]*w2[k];
        } else {
            int o6 = o-6;
            acc = conv_re_b[o6] + conv_im_b[o6];
            const float* w1 = conv_re_w + o6*PP; const float* w2 = conv_im_w + o6*PP;
            #pragma unroll 10
            for (int k=0;k<PP;k++) acc += xi[k]*w1[k] + xr[k]*w2[k];
        }
        g_h[idx] = acc + pos[l*DM + o];
    }
    gridbar();

    // ===== BN sums =====
    {
        float ls[DM], lq[DM];
        #pragma unroll
        for(int c=0;c<DM;c++){ ls[c]=0.f; lq[c]=0.f; }
        for (int j = gtid; j < ROWS; j += gsz){
            #pragma unroll
            for(int c=0;c<DM;c++){ float v=g_h[j*DM+c]; ls[c]+=v; lq[c]+=v*v; }
        }
        #pragma unroll
        for(int c=0;c<DM;c++){
            float a=ls[c], q=lq[c];
            for(int off=16;off>0;off>>=1){
                a+=__shfl_down_sync(0xffffffffu,a,off);
                q+=__shfl_down_sync(0xffffffffu,q,off);
            }
            if (lane==0 && (a!=0.f || q!=0.f)){
                atomicAdd(&g_bns[c], a);
                atomicAdd(&g_bns[DM+c], q);
            }
        }
    }
    gridbar();

    // ===== BN apply + silu =====
    {
        if (tid < DM){
            float mu  = g_bns[tid]*(1.0f/ROWS);
            float var = g_bns[DM+tid]*(1.0f/ROWS) - mu*mu;
            float sc  = rsqrtf(var+1e-6f)*bn_gamma[tid];
            sm[tid]    = sc;
            sm[DM+tid] = bn_beta[tid] - mu*sc;
        }
        __syncthreads();
        for (int idx = gtid; idx < ROWS*DM; idx += gsz){
            int c = idx % DM;
            float v = g_h[idx]*sm[c] + sm[DM+c];
            g_h[idx] = siluf_(v);
        }
        __syncthreads();
    }
    gridbar();

    // ===== layers (pipelined; no grid barriers) =====
    for (int layer = 0; layer < NL; layer++){
        // ---- wait: downstream consumer released our xz rows ----
        if (layer >= 1 && seg_s < NSEG-1) wait_ge(&g_xz_ack[bid+1], (unsigned)layer);
        // ---- rmsnorm + in_proj: 12 rows, 4 cols/thread in 2 passes ----
        {
            float* su   = sxc;
            float* srms = sxc + 160;
            const float* Wl  = in_proj_w + layer*XZW*DM;
            const float* rwl = rms_w + layer*DM;
            if (tid < SEGL*DM) su[tid] = g_h[rowbase*DM + tid];
            __syncthreads();
            if (tid < SEGL){
                float s=0.f;
                #pragma unroll
                for(int d=0;d<DM;d++){ float v=su[tid*DM+d]; s+=v*v; }
                srms[tid] = rsqrtf(s*(1.0f/DM)+1e-5f);
            }
            __syncthreads();
            float uv = 0.f;
            if (tid < SEGL*DM) uv = su[tid]*srms[tid/DM]*rwl[tid%DM];
            __syncthreads();
            if (tid < SEGL*DM) su[tid] = uv;
            __syncthreads();
            #pragma unroll
            for (int jp=0; jp<2; jp++){
                float w[2][DM];
                #pragma unroll
                for(int j2=0;j2<2;j2++){
                    const float* wp = Wl + (tid + NTH*(jp*2+j2))*DM;
                    #pragma unroll
                    for(int d=0;d<DM;d++) w[j2][d]=wp[d];
                }
                for (int r=0;r<SEGL;r++){
                    float u[DM];
                    #pragma unroll
                    for(int d=0;d<DM;d++) u[d]=su[r*DM+d];
                    #pragma unroll
                    for(int j2=0;j2<2;j2++){
                        float acc=0.f;
                        #pragma unroll
                        for(int d=0;d<DM;d++) acc += u[d]*w[j2][d];
                        g_xz[(rowbase+r)*XZW + tid + NTH*(jp*2+j2)] = acc;
                    }
                }
            }
        }
        signal_release(&g_xz_ready[bid]);         // = layer+1

        // ---- cvxp: needs halo rows from bid-1 ----
        if (seg_s > 0) wait_ge(&g_xz_ready[bid-1], (unsigned)(layer+1));
        {
            const int pair  = warp >> 1;       // 0..5
            const int split = warp & 1;
            const int r0    = pair*2;
            const int grow0 = rowbase + r0;
            const int l0    = grow0 % LP;
            const float* cwT = g_cwT + layer*4*ED;
            const float* Wx  = x_proj_w + layer*DBLW*ED;
            float part[2][DBLW];
            #pragma unroll
            for(int r=0;r<2;r++)
                #pragma unroll
                for(int t=0;t<DBLW;t++) part[r][t]=0.f;
            #pragma unroll
            for (int c=0;c<3;c++){
                int e0 = split*384 + c*128 + lane*4;
                float4 w0 = __ldg((const float4*)(cwT + 0*ED + e0));
                float4 w1 = __ldg((const float4*)(cwT + 1*ED + e0));
                float4 w2 = __ldg((const float4*)(cwT + 2*ED + e0));
                float4 b4 = __ldg((const float4*)(cwT + 3*ED + e0));
                float4 xm2 = {0,0,0,0}, xm1 = {0,0,0,0};
                if (l0>=2) xm2 = *(const float4*)(g_xz + (grow0-2)*XZW + e0);
                if (l0>=1) xm1 = *(const float4*)(g_xz + (grow0-1)*XZW + e0);
                float4 x0 = *(const float4*)(g_xz + grow0*XZW + e0);
                float4 x1 = *(const float4*)(g_xz + (grow0+1)*XZW + e0);
                float4 xc0, xc1;
                xc0.x = siluf_(b4.x + w0.x*xm2.x + w1.x*xm1.x + w2.x*x0.x);
                xc0.y = siluf_(b4.y + w0.y*xm2.y + w1.y*xm1.y + w2.y*x0.y);
                xc0.z = siluf_(b4.z + w0.z*xm2.z + w1.z*xm1.z + w2.z*x0.z);
                xc0.w = siluf_(b4.w + w0.w*xm2.w + w1.w*xm1.w + w2.w*x0.w);
                xc1.x = siluf_(b4.x + w0.x*xm1.x + w1.x*x0.x + w2.x*x1.x);
                xc1.y = siluf_(b4.y + w0.y*xm1.y + w1.y*x0.y + w2.y*x1.y);
                xc1.z = siluf_(b4.z + w0.z*xm1.z + w1.z*x0.z + w2.z*x1.z);
                xc1.w = siluf_(b4.w + w0.w*xm1.w + w1.w*x0.w + w2.w*x1.w);
                *(float4*)(sxc + r0*ED + e0)     = xc0;
                *(float4*)(sxc + (r0+1)*ED + e0) = xc1;
                #pragma unroll
                for(int t=0;t<DBLW;t++){
                    float4 wt = __ldg((const float4*)(Wx + t*ED + e0));
                    part[0][t] += wt.x*xc0.x + wt.y*xc0.y + wt.z*xc0.z + wt.w*xc0.w;
                    part[1][t] += wt.x*xc1.x + wt.y*xc1.y + wt.z*xc1.z + wt.w*xc1.w;
                }
            }
            #pragma unroll
            for(int r=0;r<2;r++)
                #pragma unroll
                for(int t=0;t<DBLW;t++){
                    float v = part[r][t];
                    for(int off=16;off>0;off>>=1) v += __shfl_down_sync(0xffffffffu, v, off);
                    if (lane==0) stmp[(split*SEGL + r0 + r)*DBLW + t] = v;
                }
        }
        __syncthreads();   // halo loads complete for all threads
        if (tid == 0){ __threadfence(); atomicAdd(&g_xz_ack[bid], 1u); }
        for (int idx = tid; idx < SEGL*DBLW; idx += NTH){
            int row = idx / DBLW, t = idx % DBLW;
            float v = stmp[row*DBLW + t] + stmp[(SEGL+row)*DBLW + t];
            sdb[row*DBLS + (t==0 ? 16 : (t-1))] = v;
        }
        __syncthreads();
        #pragma unroll
        for (int half=0; half<2; half++){
            int e = tid + half*NTH;
            float dw = dt_proj_w[layer*ED + e];
            float db = dt_proj_b[layer*ED + e];
            #pragma unroll 4
            for (int r=0;r<SEGL;r++){
                float d0 = sdb[r*DBLS + 16];
                sdl[r*ED + e] = softplusf_(d0*dw + db);
            }
        }
        __syncthreads();

        // ---- pq buffer reuse gate (once per layer) ----
        if (seg_s < NSEG-1 && layer >= 2)
            wait_ge(&g_pq_ack[bid], (unsigned)((NSEG-1-seg_s)*(layer-1)));

        // ---- local scan (h0=0): y_local in sxc; publish (P,q) ----
        #pragma unroll 1
        for (int half=0; half<2; half++){
            int e = tid + half*NTH;
            const float* ap = g_A2 + (layer*ED + e)*NS;
            float a20 = __ldg(ap);
            bool geo = true;
            #pragma unroll
            for(int n=1;n<NS;n++){
                float an = __ldg(ap+n);
                geo = geo && (fabsf(an - (float)(n+1)*a20) <= 1e-4f*fabsf(an));
            }
            float Dv = Dp[layer*ED + e];
            float st[NS], sumd = 0.f, Pp = 1.f;
            #pragma unroll
            for(int n=0;n<NS;n++) st[n]=0.f;
            float z_n = g_xz[rowbase*XZW + ED + e];
            for (int li=0; li<SEGL; li++){
                float z = z_n;
                if (li < SEGL-1) z_n = g_xz[(rowbase+li+1)*XZW + ED + e];
                float delta = sdl[li*ED + e];
                float xc    = sxc[li*ED + e];
                float dx = delta * xc;
                float4 B0 = *(const float4*)(sdb + li*DBLS);
                float4 B1 = *(const float4*)(sdb + li*DBLS + 4);
                float4 C0 = *(const float4*)(sdb + li*DBLS + 8);
                float4 C1 = *(const float4*)(sdb + li*DBLS + 12);
                float Bv[NS] = {B0.x,B0.y,B0.z,B0.w,B1.x,B1.y,B1.z,B1.w};
                float Cv[NS] = {C0.x,C0.y,C0.z,C0.w,C1.x,C1.y,C1.z,C1.w};
                float y = Dv * xc;
                float p = ex2f_(delta * a20);
                Pp *= p;
                float dan = 1.f;
                #pragma unroll
                for(int n=0;n<NS;n++){
                    if (geo) dan *= p;
                    else     dan = ex2f_(delta * __ldg(ap+n));
                    st[n] = dan*st[n] + dx*Bv[n];
                    y += st[n]*Cv[n];
                }
                sumd += delta;
                sxc[li*ED + e] = (seg_s == 0) ? (y * siluf_(z)) : y;
            }
            if (seg_s < NSEG-1){
                int base = (layer&1)*PQSTRIDE + ((seg_s*BSZ + seg_b)*NS)*ED + e;
                if (geo){
                    float Pn = 1.f;
                    #pragma unroll
                    for(int n=0;n<NS;n++){
                        Pn *= Pp;                 // exact product of per-step da
                        g_P[base + n*ED] = Pn;
                        g_q[base + n*ED] = st[n];
                    }
                } else {
                    #pragma unroll
                    for(int n=0;n<NS;n++){
                        g_P[base + n*ED] = ex2f_(__ldg(ap+n)*sumd);
                        g_q[base + n*ED] = st[n];
                    }
                }
            }
        }
        if (seg_s < NSEG-1) signal_release(&g_pq_ready[bid]);   // = layer+1

        // ---- correction: y += C * cumprod(da) * h_in, gate ----
        if (seg_s > 0){
            for (int sp = 0; sp < seg_s; sp++)
                wait_ge(&g_pq_ready[(seg_b<<3)|sp], (unsigned)(layer+1));
            #pragma unroll 1
            for (int half=0; half<2; half++){
                int e = tid + half*NTH;
                const float* ap = g_A2 + (layer*ED + e)*NS;
                float a20 = __ldg(ap);
                bool geo = true;
                #pragma unroll
                for(int n=1;n<NS;n++){
                    float an = __ldg(ap+n);
                    geo = geo && (fabsf(an - (float)(n+1)*a20) <= 1e-4f*fabsf(an));
                }
                float hin[NS];
                #pragma unroll
                for(int n=0;n<NS;n++) hin[n]=0.f;
                for (int sp = 0; sp < seg_s; sp++){
                    int base = (layer&1)*PQSTRIDE + ((sp*BSZ + seg_b)*NS)*ED + e;
                    #pragma unroll
                    for(int n=0;n<NS;n++)
                        hin[n] = g_P[base + n*ED]*hin[n] + g_q[base + n*ED];
                }
                float z_n = g_xz[rowbase*XZW + ED + e];
                if (geo){
                    float cp = 1.f;
                    for (int li=0; li<SEGL; li++){
                        float z = z_n;
                        if (li < SEGL-1) z_n = g_xz[(rowbase+li+1)*XZW + ED + e];
                        float delta = sdl[li*ED + e];
                        cp *= ex2f_(delta * a20);
                        float4 C0 = *(const float4*)(sdb + li*DBLS + 8);
                        float4 C1 = *(const float4*)(sdb + li*DBLS + 12);
                        float Cv[NS] = {C0.x,C0.y,C0.z,C0.w,C1.x,C1.y,C1.z,C1.w};
                        float acc = 0.f;
                        #pragma unroll
                        for(int n=NS-1;n>=0;n--) acc = hin[n]*Cv[n] + cp*acc;
                        float y = sxc[li*ED + e] + cp*acc;
                        sxc[li*ED + e] = y * siluf_(z);
                    }
                } else {
                    float hc[NS];
                    #pragma unroll
                    for(int n=0;n<NS;n++) hc[n]=hin[n];
                    for (int li=0; li<SEGL; li++){
                        float z = z_n;
                        if (li < SEGL-1) z_n = g_xz[(rowbase+li+1)*XZW + ED + e];
                        float delta = sdl[li*ED + e];
                        float4 C0 = *(const float4*)(sdb + li*DBLS + 8);
                        float4 C1 = *(const float4*)(sdb + li*DBLS + 12);
                        float Cv[NS] = {C0.x,C0.y,C0.z,C0.w,C1.x,C1.y,C1.z,C1.w};
                        float y = sxc[li*ED + e];
                        #pragma unroll
                        for(int n=0;n<NS;n++){
                            hc[n] *= ex2f_(delta * __ldg(ap+n));
                            y += hc[n]*Cv[n];
                        }
                        sxc[li*ED + e] = y * siluf_(z);
                    }
                }
            }
            __syncthreads();   // g_P/g_q loads complete for all threads
            if (tid == 0){
                __threadfence();
                for (int sp = 0; sp < seg_s; sp++)
                    atomicAdd(&g_pq_ack[(seg_b<<3)|sp], 1u);
            }
        }
        __syncthreads();

        // ---- out_proj ----
        {
            const int pair  = warp >> 1;
            const int split = warp & 1;
            const int r0    = pair*2;
            const float* Wo = out_proj_w + layer*DM*ED;
            float pd[2][DM];
            #pragma unroll
            for(int r=0;r<2;r++)
                #pragma unroll
                for(int d=0;d<DM;d++) pd[r][d]=0.f;
            #pragma unroll
            for (int c=0;c<3;c++){
                int e0 = split*384 + c*128 + lane*4;
                float4 y0 = *(const float4*)(sxc + r0*ED + e0);
                float4 y1 = *(const float4*)(sxc + (r0+1)*ED + e0);
                #pragma unroll
                for(int d=0;d<DM;d++){
                    float4 wd4 = __ldg((const float4*)(Wo + d*ED + e0));
                    pd[0][d] += wd4.x*y0.x + wd4.y*y0.y + wd4.z*y0.z + wd4.w*y0.w;
                    pd[1][d] += wd4.x*y1.x + wd4.y*y1.y + wd4.z*y1.z + wd4.w*y1.w;
                }
            }
            #pragma unroll
            for(int r=0;r<2;r++)
                #pragma unroll
                for(int d=0;d<DM;d++){
                    float v = pd[r][d];
                    for(int off=16;off>0;off>>=1) v += __shfl_down_sync(0xffffffffu, v, off);
                    if (lane==0) stmp[(split*SEGL + r0 + r)*DM + d] = v;
                }
        }
        __syncthreads();
        for (int idx = tid; idx < SEGL*DM; idx += NTH){
            int row = idx / DM, d = idx % DM;
            g_h[(rowbase+row)*DM + d] += stmp[row*DM + d] + stmp[(SEGL+row)*DM + d];
        }
        __syncthreads();
    }
    gridbar();

    // ===== final: mean over L + FC + ReLU =====
    {
        float* m = sm;
        for (int b = bid; b < BSZ; b += NB){
            if (tid < DM){
                float s=0.f;
                for(int l=0;l<LP;l++) s += g_h[(b*LP+l)*DM + tid];
                m[tid]=s*(1.0f/LP);
            }
            __syncthreads();
            if (tid < EMB){
                float acc = fc_b[tid];
                #pragma unroll
                for(int d=0;d<DM;d++) acc += m[d]*fc_w[tid*DM+d];
                out[b*EMB+tid] = fmaxf(acc,0.0f);
            }
            __syncthreads();
        }
    }
}

// ---------------- launch ----------------
extern "C" void kernel_launch(void* const* d_in, const int* in_sizes, int n_in,
                              void* d_out, int out_size){
    const float* x          = (const float*)d_in[0];
    const float* conv_re_w  = (const float*)d_in[1];
    const float* conv_re_b  = (const float*)d_in[2];
    const float* conv_im_w  = (const float*)d_in[3];
    const float* conv_im_b  = (const float*)d_in[4];
    const float* pos        = (const float*)d_in[5];
    const float* bn_gamma   = (const float*)d_in[6];
    const float* bn_beta    = (const float*)d_in[7];
    const float* rms_w      = (const float*)d_in[8];
    const float* in_proj_w  = (const float*)d_in[9];
    const float* conv1d_w   = (const float*)d_in[10];
    const float* conv1d_b   = (const float*)d_in[11];
    const float* x_proj_w   = (const float*)d_in[12];
    const float* dt_proj_w  = (const float*)d_in[13];
    const float* dt_proj_b  = (const float*)d_in[14];
    const float* A_log      = (const float*)d_in[15];
    const float* Dp         = (const float*)d_in[16];
    const float* out_proj_w = (const float*)d_in[17];
    const float* fc_w       = (const float*)d_in[18];
    const float* fc_b       = (const float*)d_in[19];
    float* out = (float*)d_out;

    size_t dynbytes = (size_t)DYNF * sizeof(float);
    cudaFuncSetAttribute(k_mega, cudaFuncAttributeMaxDynamicSharedMemorySize, (int)dynbytes);

    k_mega<<<NBLK, NTH, dynbytes>>>(x, conv_re_w, conv_re_b, conv_im_w, conv_im_b, pos,
                         bn_gamma, bn_beta, rms_w, in_proj_w, conv1d_w, conv1d_b,
                         x_proj_w, dt_proj_w, dt_proj_b, A_log, Dp, out_proj_w,
                         fc_w, fc_b, out);
}

// round 14
// speedup vs baseline: 1.2445x; 1.2445x over previous
#include <cuda_runtime.h>

#define BSZ 32
#define LP 96
#define DM 12
#define ED 768
#define NS 8
#define NL 10
#define EMB 256
#define PP 50
#define ROWS (BSZ*LP)      // 3072
#define XZW (2*ED)         // 1536
#define DBLW 17
#define DBLS 20
#define NTH 768
#define NBLK 128
#define NSEG 4
#define SEGL 24
#define PQSTRIDE ((NSEG-1)*BSZ*NS*ED)

// smem layout (floats)
#define S_XC   0
#define S_DL   (SEGL*ED)                 // 18432
#define S_DB   (2*SEGL*ED)               // 36864
#define S_TMP  (2*SEGL*ED + SEGL*DBLS)   // 37344
#define DYNF   (S_TMP + 2*SEGL*DBLW + 32)

// ---------------- scratch ----------------
__device__ __align__(16) float g_h[ROWS*DM];
__device__ __align__(16) float g_xz[ROWS*XZW];
__device__ __align__(16) float g_P[2*PQSTRIDE];
__device__ __align__(16) float g_q[2*PQSTRIDE];
__device__ __align__(16) float g_A2[NL*ED*NS];
__device__ __align__(16) float g_cwT[NL*4*ED];
__device__ float g_bns[2*DM];
__device__ unsigned g_xz_ready[NBLK];
__device__ unsigned g_xz_ack[NBLK];
__device__ unsigned g_pq_ready[NBLK];
__device__ unsigned g_pq_ack[NBLK];
__device__ volatile unsigned g_bar_gen;
__device__ unsigned g_bar_cnt;

// ---------------- fast math ----------------
__device__ __forceinline__ float ex2f_(float x){ float y; asm("ex2.approx.f32 %0, %1;":"=f"(y):"f"(x)); return y; }
__device__ __forceinline__ float lg2f_(float x){ float y; asm("lg2.approx.f32 %0, %1;":"=f"(y):"f"(x)); return y; }
__device__ __forceinline__ float rcpf_(float x){ float y; asm("rcp.approx.f32 %0, %1;":"=f"(y):"f"(x)); return y; }
#define L2E 1.4426950408889634f
#define LN2 0.6931471805599453f
__device__ __forceinline__ float sigmoidf_(float x){ return rcpf_(1.0f + ex2f_(-x*L2E)); }
__device__ __forceinline__ float siluf_(float x){ return x * sigmoidf_(x); }
__device__ __forceinline__ float softplusf_(float x){
    return (x > 20.0f) ? x : LN2*lg2f_(1.0f + ex2f_(x*L2E));
}

// ---------------- sync primitives ----------------
__device__ __forceinline__ void gridbar(){
    __threadfence();
    __syncthreads();
    if (threadIdx.x == 0){
        unsigned gen = g_bar_gen;
        unsigned old = atomicAdd(&g_bar_cnt, 1u);
        if (old == gridDim.x - 1u){
            g_bar_cnt = 0u;
            __threadfence();
            g_bar_gen = gen + 1u;
        } else {
            while (g_bar_gen == gen) __nanosleep(20);
        }
        __threadfence();
    }
    __syncthreads();
}
__device__ __forceinline__ void wait_ge(unsigned* ctr, unsigned target){
    __syncthreads();
    if (threadIdx.x == 0){
        volatile unsigned* p = (volatile unsigned*)ctr;
        unsigned v = *p;
        while ((int)(v - target) < 0){ __nanosleep(8); v = *p; }
        __threadfence();   // acquire: invalidates stale L1 for this SM
    }
    __syncthreads();
}
// release: ALL threads fence their stores, then barrier, then flag
__device__ __forceinline__ void signal_release(unsigned* ctr){
    __threadfence();
    __syncthreads();
    if (threadIdx.x == 0) atomicAdd(ctr, 1u);
}

// ---------------- megakernel ----------------
__global__ void __launch_bounds__(NTH,1) k_mega(
    const float* __restrict__ x,
    const float* __restrict__ conv_re_w, const float* __restrict__ conv_re_b,
    const float* __restrict__ conv_im_w, const float* __restrict__ conv_im_b,
    const float* __restrict__ pos,
    const float* __restrict__ bn_gamma, const float* __restrict__ bn_beta,
    const float* __restrict__ rms_w,
    const float* __restrict__ in_proj_w,
    const float* __restrict__ conv1d_w, const float* __restrict__ conv1d_b,
    const float* __restrict__ x_proj_w,
    const float* __restrict__ dt_proj_w, const float* __restrict__ dt_proj_b,
    const float* __restrict__ A_log,  const float* __restrict__ Dp,
    const float* __restrict__ out_proj_w,
    const float* __restrict__ fc_w, const float* __restrict__ fc_b,
    float* __restrict__ out)
{
    extern __shared__ float sm[];
    float* sxc  = sm + S_XC;
    float* sdl  = sm + S_DL;
    float* sdb  = sm + S_DB;
    float* stmp = sm + S_TMP;
    const int NB  = gridDim.x;
    const int bid = blockIdx.x;
    const int tid = threadIdx.x;
    const int gsz = NB*NTH;
    const int gtid = bid*NTH + tid;
    const int warp = tid >> 5, lane = tid & 31;

    const int seg_b = bid >> 2;            // batch
    const int seg_s = bid & 3;             // quarter
    const int rowbase = bid*SEGL;

    // ===== phase 0 =====
    if (tid == 0){
        g_xz_ready[bid]=0u; g_xz_ack[bid]=0u;
        g_pq_ready[bid]=0u; g_pq_ack[bid]=0u;
    }
    for (int i = gtid; i < NL*ED*NS; i += gsz) g_A2[i] = -expf(A_log[i]) * L2E;
    for (int i = gtid; i < NL*ED; i += gsz){
        int layer = i / ED, e = i % ED;
        const float* wp = conv1d_w + i*3;
        float* dst = g_cwT + layer*4*ED;
        dst[0*ED+e] = wp[0];
        dst[1*ED+e] = wp[1];
        dst[2*ED+e] = wp[2];
        dst[3*ED+e] = conv1d_b[i];
    }
    if (gtid < 2*DM) g_bns[gtid] = 0.f;
    for (int idx = gtid; idx < ROWS*DM; idx += gsz){
        int row = idx / DM, o = idx % DM;
        int b = row / LP, l = row % LP;
        const float* xr = x + b*(2*LP*PP) + l*PP;
        const float* xi = xr + LP*PP;
        float acc;
        if (o < 6){
            acc = conv_re_b[o] - conv_im_b[o];
            const float* w1 = conv_re_w + o*PP; const float* w2 = conv_im_w + o*PP;
            #pragma unroll 10
            for (int k=0;k<PP;k++) acc += xr[k]*w1[k] - xi[k]*w2[k];
        } else {
            int o6 = o-6;
            acc = conv_re_b[o6] + conv_im_b[o6];
            const float* w1 = conv_re_w + o6*PP; const float* w2 = conv_im_w + o6*PP;
            #pragma unroll 10
            for (int k=0;k<PP;k++) acc += xi[k]*w1[k] + xr[k]*w2[k];
        }
        g_h[idx] = acc + pos[l*DM + o];
    }
    gridbar();

    // ===== BN sums =====
    {
        float ls[DM], lq[DM];
        #pragma unroll
        for(int c=0;c<DM;c++){ ls[c]=0.f; lq[c]=0.f; }
        for (int j = gtid; j < ROWS; j += gsz){
            #pragma unroll
            for(int c=0;c<DM;c++){ float v=g_h[j*DM+c]; ls[c]+=v; lq[c]+=v*v; }
        }
        #pragma unroll
        for(int c=0;c<DM;c++){
            float a=ls[c], q=lq[c];
            for(int off=16;off>0;off>>=1){
                a+=__shfl_down_sync(0xffffffffu,a,off);
                q+=__shfl_down_sync(0xffffffffu,q,off);
            }
            if (lane==0 && (a!=0.f || q!=0.f)){
                atomicAdd(&g_bns[c], a);
                atomicAdd(&g_bns[DM+c], q);
            }
        }
    }
    gridbar();

    // ===== BN apply + silu =====
    {
        if (tid < DM){
            float mu  = g_bns[tid]*(1.0f/ROWS);
            float var = g_bns[DM+tid]*(1.0f/ROWS) - mu*mu;
            float sc  = rsqrtf(var+1e-6f)*bn_gamma[tid];
            sm[tid]    = sc;
            sm[DM+tid] = bn_beta[tid] - mu*sc;
        }
        __syncthreads();
        for (int idx = gtid; idx < ROWS*DM; idx += gsz){
            int c = idx % DM;
            float v = g_h[idx]*sm[c] + sm[DM+c];
            g_h[idx] = siluf_(v);
        }
        __syncthreads();
    }
    gridbar();

    // ===== layers (pipelined; no grid barriers) =====
    for (int layer = 0; layer < NL; layer++){
        // ---- wait: downstream consumer released our xz rows ----
        if (layer >= 1 && seg_s < NSEG-1) wait_ge(&g_xz_ack[bid+1], (unsigned)layer);
        // ---- rmsnorm + in_proj: 24 rows, 2 cols/thread, float4 weights ----
        {
            float* su   = sxc;
            float* srms = sxc + 320;
            const float* Wl  = in_proj_w + layer*XZW*DM;
            const float* rwl = rms_w + layer*DM;
            if (tid < SEGL*DM) su[tid] = g_h[rowbase*DM + tid];
            __syncthreads();
            if (tid < SEGL){
                float s=0.f;
                #pragma unroll
                for(int d=0;d<DM;d++){ float v=su[tid*DM+d]; s+=v*v; }
                srms[tid] = rsqrtf(s*(1.0f/DM)+1e-5f);
            }
            __syncthreads();
            float uv = 0.f;
            if (tid < SEGL*DM) uv = su[tid]*srms[tid/DM]*rwl[tid%DM];
            __syncthreads();
            if (tid < SEGL*DM) su[tid] = uv;
            __syncthreads();
            float w[2][DM];
            #pragma unroll
            for(int j=0;j<2;j++){
                const float* wp = Wl + (tid + NTH*j)*DM;   // 48B-aligned row
                float4 wa = __ldg((const float4*)(wp));
                float4 wb = __ldg((const float4*)(wp+4));
                float4 wc = __ldg((const float4*)(wp+8));
                w[j][0]=wa.x; w[j][1]=wa.y; w[j][2]=wa.z; w[j][3]=wa.w;
                w[j][4]=wb.x; w[j][5]=wb.y; w[j][6]=wb.z; w[j][7]=wb.w;
                w[j][8]=wc.x; w[j][9]=wc.y; w[j][10]=wc.z; w[j][11]=wc.w;
            }
            for (int r=0;r<SEGL;r++){
                float u[DM];
                #pragma unroll
                for(int d=0;d<DM;d++) u[d]=su[r*DM+d];
                #pragma unroll
                for(int j=0;j<2;j++){
                    float acc=0.f;
                    #pragma unroll
                    for(int d=0;d<DM;d++) acc += u[d]*w[j][d];
                    g_xz[(rowbase+r)*XZW + tid + NTH*j] = acc;
                }
            }
        }
        signal_release(&g_xz_ready[bid]);         // = layer+1

        // ---- cvxp: needs halo rows from bid-1 ----
        if (seg_s > 0) wait_ge(&g_xz_ready[bid-1], (unsigned)(layer+1));
        {
            const int pair  = warp >> 1;       // 0..11
            const int split = warp & 1;
            const int r0    = pair*2;
            const int grow0 = rowbase + r0;
            const int l0    = grow0 % LP;
            const float* cwT = g_cwT + layer*4*ED;
            const float* Wx  = x_proj_w + layer*DBLW*ED;
            float part[2][DBLW];
            #pragma unroll
            for(int r=0;r<2;r++)
                #pragma unroll
                for(int t=0;t<DBLW;t++) part[r][t]=0.f;
            #pragma unroll
            for (int c=0;c<3;c++){
                int e0 = split*384 + c*128 + lane*4;
                float4 w0 = __ldg((const float4*)(cwT + 0*ED + e0));
                float4 w1 = __ldg((const float4*)(cwT + 1*ED + e0));
                float4 w2 = __ldg((const float4*)(cwT + 2*ED + e0));
                float4 b4 = __ldg((const float4*)(cwT + 3*ED + e0));
                float4 xm2 = {0,0,0,0}, xm1 = {0,0,0,0};
                if (l0>=2) xm2 = *(const float4*)(g_xz + (grow0-2)*XZW + e0);
                if (l0>=1) xm1 = *(const float4*)(g_xz + (grow0-1)*XZW + e0);
                float4 x0 = *(const float4*)(g_xz + grow0*XZW + e0);
                float4 x1 = *(const float4*)(g_xz + (grow0+1)*XZW + e0);
                float4 xc0, xc1;
                xc0.x = siluf_(b4.x + w0.x*xm2.x + w1.x*xm1.x + w2.x*x0.x);
                xc0.y = siluf_(b4.y + w0.y*xm2.y + w1.y*xm1.y + w2.y*x0.y);
                xc0.z = siluf_(b4.z + w0.z*xm2.z + w1.z*xm1.z + w2.z*x0.z);
                xc0.w = siluf_(b4.w + w0.w*xm2.w + w1.w*xm1.w + w2.w*x0.w);
                xc1.x = siluf_(b4.x + w0.x*xm1.x + w1.x*x0.x + w2.x*x1.x);
                xc1.y = siluf_(b4.y + w0.y*xm1.y + w1.y*x0.y + w2.y*x1.y);
                xc1.z = siluf_(b4.z + w0.z*xm1.z + w1.z*x0.z + w2.z*x1.z);
                xc1.w = siluf_(b4.w + w0.w*xm1.w + w1.w*x0.w + w2.w*x1.w);
                *(float4*)(sxc + r0*ED + e0)     = xc0;
                *(float4*)(sxc + (r0+1)*ED + e0) = xc1;
                #pragma unroll
                for(int t=0;t<DBLW;t++){
                    float4 wt = __ldg((const float4*)(Wx + t*ED + e0));
                    part[0][t] += wt.x*xc0.x + wt.y*xc0.y + wt.z*xc0.z + wt.w*xc0.w;
                    part[1][t] += wt.x*xc1.x + wt.y*xc1.y + wt.z*xc1.z + wt.w*xc1.w;
                }
            }
            #pragma unroll
            for(int r=0;r<2;r++)
                #pragma unroll
                for(int t=0;t<DBLW;t++){
                    float v = part[r][t];
                    for(int off=16;off>0;off>>=1) v += __shfl_down_sync(0xffffffffu, v, off);
                    if (lane==0) stmp[(split*SEGL + r0 + r)*DBLW + t] = v;
                }
        }
        __syncthreads();   // all halo loads complete
        if (tid == 0){ __threadfence(); atomicAdd(&g_xz_ack[bid], 1u); }
        for (int idx = tid; idx < SEGL*DBLW; idx += NTH){
            int row = idx / DBLW, t = idx % DBLW;
            float v = stmp[row*DBLW + t] + stmp[(SEGL+row)*DBLW + t];
            sdb[row*DBLS + (t==0 ? 16 : (t-1))] = v;
        }
        __syncthreads();
        {
            float dw = dt_proj_w[layer*ED + tid];
            float db = dt_proj_b[layer*ED + tid];
            #pragma unroll 4
            for (int r=0;r<SEGL;r++){
                float d0 = sdb[r*DBLS + 16];
                sdl[r*ED + tid] = softplusf_(d0*dw + db);
            }
        }
        __syncthreads();

        // ---- local scan (h0=0): y_local in sxc; publish (P,q) ----
        int e = tid;
        float a2[NS];
        {
            const float* ap = g_A2 + (layer*ED + e)*NS;
            #pragma unroll
            for(int n=0;n<NS;n++) a2[n]=ap[n];
        }
        bool geo = true;
        #pragma unroll
        for(int n=1;n<NS;n++)
            geo = geo && (fabsf(a2[n] - (float)(n+1)*a2[0]) <= 1e-4f*fabsf(a2[n]));
        {
            float Dv = Dp[layer*ED + e];
            float st[NS], sumd = 0.f, Pp = 1.f;
            #pragma unroll
            for(int n=0;n<NS;n++) st[n]=0.f;
            float z_n = (seg_s == 0) ? g_xz[rowbase*XZW + ED + e] : 0.f;
            for (int li=0; li<SEGL; li++){
                float delta = sdl[li*ED + e];
                float xc    = sxc[li*ED + e];
                float dx = delta * xc;
                float4 B0 = *(const float4*)(sdb + li*DBLS);
                float4 B1 = *(const float4*)(sdb + li*DBLS + 4);
                float4 C0 = *(const float4*)(sdb + li*DBLS + 8);
                float4 C1 = *(const float4*)(sdb + li*DBLS + 12);
                float Bv[NS] = {B0.x,B0.y,B0.z,B0.w,B1.x,B1.y,B1.z,B1.w};
                float Cv[NS] = {C0.x,C0.y,C0.z,C0.w,C1.x,C1.y,C1.z,C1.w};
                float y = Dv * xc;
                float p = ex2f_(delta * a2[0]);
                Pp *= p;
                float dan = 1.f;
                #pragma unroll
                for(int n=0;n<NS;n++){
                    if (geo) dan *= p;
                    else     dan = ex2f_(delta * a2[n]);
                    st[n] = dan*st[n] + dx*Bv[n];
                    y += st[n]*Cv[n];
                }
                sumd += delta;
                if (seg_s == 0){
                    float z = z_n;
                    if (li < SEGL-1) z_n = g_xz[(rowbase+li+1)*XZW + ED + e];
                    sxc[li*ED + e] = y * siluf_(z);
                } else {
                    sxc[li*ED + e] = y;
                }
            }
            if (seg_s < NSEG-1){
                if (layer >= 2) wait_ge(&g_pq_ack[bid], (unsigned)((NSEG-1-seg_s)*(layer-1)));
                int base = (layer&1)*PQSTRIDE + ((seg_s*BSZ + seg_b)*NS)*ED + e;
                if (geo){
                    float Pn = 1.f;
                    #pragma unroll
                    for(int n=0;n<NS;n++){
                        Pn *= Pp;                 // exact product of per-step da
                        g_P[base + n*ED] = Pn;
                        g_q[base + n*ED] = st[n];
                    }
                } else {
                    #pragma unroll
                    for(int n=0;n<NS;n++){
                        g_P[base + n*ED] = ex2f_(a2[n]*sumd);
                        g_q[base + n*ED] = st[n];
                    }
                }
                signal_release(&g_pq_ready[bid]);   // = layer+1
            }
        }

        // ---- correction: y += C * cumprod(da) * h_in, gate ----
        if (seg_s > 0){
            for (int sp = 0; sp < seg_s; sp++)
                wait_ge(&g_pq_ready[(seg_b<<2)|sp], (unsigned)(layer+1));
            float hin[NS];
            #pragma unroll
            for(int n=0;n<NS;n++) hin[n]=0.f;
            for (int sp = 0; sp < seg_s; sp++){
                int base = (layer&1)*PQSTRIDE + ((sp*BSZ + seg_b)*NS)*ED + e;
                #pragma unroll
                for(int n=0;n<NS;n++)
                    hin[n] = g_P[base + n*ED]*hin[n] + g_q[base + n*ED];
            }
            float z_n = g_xz[rowbase*XZW + ED + e];
            if (geo){
                float cp = 1.f;
                for (int li=0; li<SEGL; li++){
                    float z = z_n;
                    if (li < SEGL-1) z_n = g_xz[(rowbase+li+1)*XZW + ED + e];
                    float delta = sdl[li*ED + e];
                    cp *= ex2f_(delta * a2[0]);
                    float4 C0 = *(const float4*)(sdb + li*DBLS + 8);
                    float4 C1 = *(const float4*)(sdb + li*DBLS + 12);
                    float Cv[NS] = {C0.x,C0.y,C0.z,C0.w,C1.x,C1.y,C1.z,C1.w};
                    float acc = 0.f;
                    #pragma unroll
                    for(int n=NS-1;n>=0;n--) acc = hin[n]*Cv[n] + cp*acc;
                    float y = sxc[li*ED + e] + cp*acc;
                    sxc[li*ED + e] = y * siluf_(z);
                }
            } else {
                float hc[NS];
                #pragma unroll
                for(int n=0;n<NS;n++) hc[n]=hin[n];
                for (int li=0; li<SEGL; li++){
                    float z = z_n;
                    if (li < SEGL-1) z_n = g_xz[(rowbase+li+1)*XZW + ED + e];
                    float delta = sdl[li*ED + e];
                    float4 C0 = *(const float4*)(sdb + li*DBLS + 8);
                    float4 C1 = *(const float4*)(sdb + li*DBLS + 12);
                    float Cv[NS] = {C0.x,C0.y,C0.z,C0.w,C1.x,C1.y,C1.z,C1.w};
                    float y = sxc[li*ED + e];
                    #pragma unroll
                    for(int n=0;n<NS;n++){
                        hc[n] *= ex2f_(delta * a2[n]);
                        y += hc[n]*Cv[n];
                    }
                    sxc[li*ED + e] = y * siluf_(z);
                }
            }
            __syncthreads();   // g_P/g_q loads complete
            if (tid == 0){
                __threadfence();
                for (int sp = 0; sp < seg_s; sp++)
                    atomicAdd(&g_pq_ack[(seg_b<<2)|sp], 1u);
            }
        }
        __syncthreads();

        // ---- out_proj ----
        {
            const int pair  = warp >> 1;
            const int split = warp & 1;
            const int r0    = pair*2;
            const float* Wo = out_proj_w + layer*DM*ED;
            float pd[2][DM];
            #pragma unroll
            for(int r=0;r<2;r++)
                #pragma unroll
                for(int d=0;d<DM;d++) pd[r][d]=0.f;
            #pragma unroll
            for (int c=0;c<3;c++){
                int e0 = split*384 + c*128 + lane*4;
                float4 y0 = *(const float4*)(sxc + r0*ED + e0);
                float4 y1 = *(const float4*)(sxc + (r0+1)*ED + e0);
                #pragma unroll
                for(int d=0;d<DM;d++){
                    float4 wd4 = __ldg((const float4*)(Wo + d*ED + e0));
                    pd[0][d] += wd4.x*y0.x + wd4.y*y0.y + wd4.z*y0.z + wd4.w*y0.w;
                    pd[1][d] += wd4.x*y1.x + wd4.y*y1.y + wd4.z*y1.z + wd4.w*y1.w;
                }
            }
            #pragma unroll
            for(int r=0;r<2;r++)
                #pragma unroll
                for(int d=0;d<DM;d++){
                    float v = pd[r][d];
                    for(int off=16;off>0;off>>=1) v += __shfl_down_sync(0xffffffffu, v, off);
                    if (lane==0) stmp[(split*SEGL + r0 + r)*DM + d] = v;
                }
        }
        __syncthreads();
        for (int idx = tid; idx < SEGL*DM; idx += NTH){
            int row = idx / DM, d = idx % DM;
            g_h[(rowbase+row)*DM + d] += stmp[row*DM + d] + stmp[(SEGL+row)*DM + d];
        }
        __syncthreads();
    }
    gridbar();

    // ===== final: mean over L + FC + ReLU =====
    {
        float* m = sm;
        for (int b = bid; b < BSZ; b += NB){
            if (tid < DM){
                float s=0.f;
                for(int l=0;l<LP;l++) s += g_h[(b*LP+l)*DM + tid];
                m[tid]=s*(1.0f/LP);
            }
            __syncthreads();
            if (tid < EMB){
                float acc = fc_b[tid];
                #pragma unroll
                for(int d=0;d<DM;d++) acc += m[d]*fc_w[tid*DM+d];
                out[b*EMB+tid] = fmaxf(acc,0.0f);
            }
            __syncthreads();
        }
    }
}

// ---------------- launch ----------------
extern "C" void kernel_launch(void* const* d_in, const int* in_sizes, int n_in,
                              void* d_out, int out_size){
    const float* x          = (const float*)d_in[0];
    const float* conv_re_w  = (const float*)d_in[1];
    const float* conv_re_b  = (const float*)d_in[2];
    const float* conv_im_w  = (const float*)d_in[3];
    const float* conv_im_b  = (const float*)d_in[4];
    const float* pos        = (const float*)d_in[5];
    const float* bn_gamma   = (const float*)d_in[6];
    const float* bn_beta    = (const float*)d_in[7];
    const float* rms_w      = (const float*)d_in[8];
    const float* in_proj_w  = (const float*)d_in[9];
    const float* conv1d_w   = (const float*)d_in[10];
    const float* conv1d_b   = (const float*)d_in[11];
    const float* x_proj_w   = (const float*)d_in[12];
    const float* dt_proj_w  = (const float*)d_in[13];
    const float* dt_proj_b  = (const float*)d_in[14];
    const float* A_log      = (const float*)d_in[15];
    const float* Dp         = (const float*)d_in[16];
    const float* out_proj_w = (const float*)d_in[17];
    const float* fc_w       = (const float*)d_in[18];
    const float* fc_b       = (const float*)d_in[19];
    float* out = (float*)d_out;

    size_t dynbytes = (size_t)DYNF * sizeof(float);
    cudaFuncSetAttribute(k_mega, cudaFuncAttributeMaxDynamicSharedMemorySize, (int)dynbytes);

    k_mega<<<NBLK, NTH, dynbytes>>>(x, conv_re_w, conv_re_b, conv_im_w, conv_im_b, pos,
                         bn_gamma, bn_beta, rms_w, in_proj_w, conv1d_w, conv1d_b,
                         x_proj_w, dt_proj_w, dt_proj_b, A_log, Dp, out_proj_w,
                         fc_w, fc_b, out);
}

// round 15
// speedup vs baseline: 1.4213x; 1.1420x over previous
#include <cuda_runtime.h>

#define BSZ 32
#define LP 96
#define DM 12
#define ED 768
#define NS 8
#define NL 10
#define EMB 256
#define PP 50
#define ROWS (BSZ*LP)      // 3072
#define XZW (2*ED)         // 1536
#define DBLW 17
#define DBLS 20
#define NTH 768
#define NBLK 128
#define NSEG 4
#define SEGL 24
#define PQSTRIDE ((NSEG-1)*BSZ*NS*ED)
#define XZBUF (ROWS*XZW)

// smem layout (floats)
#define S_XC   0
#define S_DL   (SEGL*ED)                 // 18432
#define S_DB   (2*SEGL*ED)               // 36864
#define S_TMP  (2*SEGL*ED + SEGL*DBLS)   // 37344
#define DYNF   (S_TMP + 2*SEGL*DBLW + 32)

typedef unsigned long long ull;

// ---------------- scratch ----------------
__device__ __align__(16) float g_h[ROWS*DM];
__device__ __align__(16) float g_xz[2*XZBUF];     // layer-parity double buffer
__device__ __align__(16) float g_P[2*PQSTRIDE];
__device__ __align__(16) float g_q[2*PQSTRIDE];
__device__ __align__(16) float g_A2[NL*ED*NS];
__device__ __align__(16) float g_cwT[NL*4*ED];
__device__ float g_bns[2*DM];
__device__ unsigned g_xz_ready[NBLK];
__device__ unsigned g_xz_ack[NBLK];
__device__ unsigned g_pq_ready[NBLK];
__device__ unsigned g_pq_ack[NBLK];
__device__ volatile unsigned g_bar_gen;
__device__ unsigned g_bar_cnt;

// ---------------- fast math ----------------
__device__ __forceinline__ float ex2f_(float x){ float y; asm("ex2.approx.f32 %0, %1;":"=f"(y):"f"(x)); return y; }
__device__ __forceinline__ float lg2f_(float x){ float y; asm("lg2.approx.f32 %0, %1;":"=f"(y):"f"(x)); return y; }
__device__ __forceinline__ float rcpf_(float x){ float y; asm("rcp.approx.f32 %0, %1;":"=f"(y):"f"(x)); return y; }
#define L2E 1.4426950408889634f
#define LN2 0.6931471805599453f
__device__ __forceinline__ float sigmoidf_(float x){ return rcpf_(1.0f + ex2f_(-x*L2E)); }
__device__ __forceinline__ float siluf_(float x){ return x * sigmoidf_(x); }
__device__ __forceinline__ float softplusf_(float x){
    return (x > 20.0f) ? x : LN2*lg2f_(1.0f + ex2f_(x*L2E));
}
// packed f32x2 helpers
__device__ __forceinline__ ull pk2_(float lo, float hi){ ull v; asm("mov.b64 %0, {%1,%2};" : "=l"(v) : "f"(lo), "f"(hi)); return v; }
__device__ __forceinline__ void upk2_(float& lo, float& hi, ull v){ asm("mov.b64 {%0,%1}, %2;" : "=f"(lo), "=f"(hi) : "l"(v)); }
__device__ __forceinline__ ull mul2_(ull a, ull b){ ull d; asm("mul.rn.f32x2 %0, %1, %2;" : "=l"(d) : "l"(a), "l"(b)); return d; }
__device__ __forceinline__ ull fma2_(ull a, ull b, ull c){ ull d; asm("fma.rn.f32x2 %0, %1, %2, %3;" : "=l"(d) : "l"(a), "l"(b), "l"(c)); return d; }

// ---------------- sync primitives ----------------
__device__ __forceinline__ void gridbar(){
    __threadfence();
    __syncthreads();
    if (threadIdx.x == 0){
        unsigned gen = g_bar_gen;
        unsigned old = atomicAdd(&g_bar_cnt, 1u);
        if (old == gridDim.x - 1u){
            g_bar_cnt = 0u;
            __threadfence();
            g_bar_gen = gen + 1u;
        } else {
            while (g_bar_gen == gen) __nanosleep(20);
        }
        __threadfence();
    }
    __syncthreads();
}
__device__ __forceinline__ void wait_ge(unsigned* ctr, unsigned target){
    __syncthreads();
    if (threadIdx.x == 0){
        volatile unsigned* p = (volatile unsigned*)ctr;
        unsigned v = *p;
        while ((int)(v - target) < 0){ __nanosleep(8); v = *p; }
        __threadfence();   // acquire
    }
    __syncthreads();
}
__device__ __forceinline__ void signal_release(unsigned* ctr){
    __threadfence();
    __syncthreads();
    if (threadIdx.x == 0) atomicAdd(ctr, 1u);
}

// ---------------- megakernel ----------------
__global__ void __launch_bounds__(NTH,1) k_mega(
    const float* __restrict__ x,
    const float* __restrict__ conv_re_w, const float* __restrict__ conv_re_b,
    const float* __restrict__ conv_im_w, const float* __restrict__ conv_im_b,
    const float* __restrict__ pos,
    const float* __restrict__ bn_gamma, const float* __restrict__ bn_beta,
    const float* __restrict__ rms_w,
    const float* __restrict__ in_proj_w,
    const float* __restrict__ conv1d_w, const float* __restrict__ conv1d_b,
    const float* __restrict__ x_proj_w,
    const float* __restrict__ dt_proj_w, const float* __restrict__ dt_proj_b,
    const float* __restrict__ A_log,  const float* __restrict__ Dp,
    const float* __restrict__ out_proj_w,
    const float* __restrict__ fc_w, const float* __restrict__ fc_b,
    float* __restrict__ out)
{
    extern __shared__ float sm[];
    float* sxc  = sm + S_XC;
    float* sdl  = sm + S_DL;
    float* sdb  = sm + S_DB;
    float* stmp = sm + S_TMP;
    const int NB  = gridDim.x;
    const int bid = blockIdx.x;
    const int tid = threadIdx.x;
    const int gsz = NB*NTH;
    const int gtid = bid*NTH + tid;
    const int warp = tid >> 5, lane = tid & 31;

    const int seg_b = bid >> 2;            // batch
    const int seg_s = bid & 3;             // quarter
    const int rowbase = bid*SEGL;

    // ===== phase 0 =====
    if (tid == 0){
        g_xz_ready[bid]=0u; g_xz_ack[bid]=0u;
        g_pq_ready[bid]=0u; g_pq_ack[bid]=0u;
    }
    for (int i = gtid; i < NL*ED*NS; i += gsz) g_A2[i] = -expf(A_log[i]) * L2E;
    for (int i = gtid; i < NL*ED; i += gsz){
        int layer = i / ED, e = i % ED;
        const float* wp = conv1d_w + i*3;
        float* dst = g_cwT + layer*4*ED;
        dst[0*ED+e] = wp[0];
        dst[1*ED+e] = wp[1];
        dst[2*ED+e] = wp[2];
        dst[3*ED+e] = conv1d_b[i];
    }
    if (gtid < 2*DM) g_bns[gtid] = 0.f;
    for (int idx = gtid; idx < ROWS*DM; idx += gsz){
        int row = idx / DM, o = idx % DM;
        int b = row / LP, l = row % LP;
        const float* xr = x + b*(2*LP*PP) + l*PP;
        const float* xi = xr + LP*PP;
        float acc;
        if (o < 6){
            acc = conv_re_b[o] - conv_im_b[o];
            const float* w1 = conv_re_w + o*PP; const float* w2 = conv_im_w + o*PP;
            #pragma unroll 10
            for (int k=0;k<PP;k++) acc += xr[k]*w1[k] - xi[k]*w2[k];
        } else {
            int o6 = o-6;
            acc = conv_re_b[o6] + conv_im_b[o6];
            const float* w1 = conv_re_w + o6*PP; const float* w2 = conv_im_w + o6*PP;
            #pragma unroll 10
            for (int k=0;k<PP;k++) acc += xi[k]*w1[k] + xr[k]*w2[k];
        }
        g_h[idx] = acc + pos[l*DM + o];
    }
    gridbar();

    // ===== BN sums =====
    {
        float ls[DM], lq[DM];
        #pragma unroll
        for(int c=0;c<DM;c++){ ls[c]=0.f; lq[c]=0.f; }
        for (int j = gtid; j < ROWS; j += gsz){
            #pragma unroll
            for(int c=0;c<DM;c++){ float v=g_h[j*DM+c]; ls[c]+=v; lq[c]+=v*v; }
        }
        #pragma unroll
        for(int c=0;c<DM;c++){
            float a=ls[c], q=lq[c];
            for(int off=16;off>0;off>>=1){
                a+=__shfl_down_sync(0xffffffffu,a,off);
                q+=__shfl_down_sync(0xffffffffu,q,off);
            }
            if (lane==0 && (a!=0.f || q!=0.f)){
                atomicAdd(&g_bns[c], a);
                atomicAdd(&g_bns[DM+c], q);
            }
        }
    }
    gridbar();

    // ===== BN apply + silu =====
    {
        if (tid < DM){
            float mu  = g_bns[tid]*(1.0f/ROWS);
            float var = g_bns[DM+tid]*(1.0f/ROWS) - mu*mu;
            float sc  = rsqrtf(var+1e-6f)*bn_gamma[tid];
            sm[tid]    = sc;
            sm[DM+tid] = bn_beta[tid] - mu*sc;
        }
        __syncthreads();
        for (int idx = gtid; idx < ROWS*DM; idx += gsz){
            int c = idx % DM;
            float v = g_h[idx]*sm[c] + sm[DM+c];
            g_h[idx] = siluf_(v);
        }
        __syncthreads();
    }
    gridbar();

    // ===== layers (pipelined; no grid barriers) =====
    for (int layer = 0; layer < NL; layer++){
        float* xzb = g_xz + (layer&1)*XZBUF;   // this layer's xz buffer
        // ---- WAR wait relaxed by double buffer: readers of layer-2 done ----
        if (layer >= 2 && seg_s < NSEG-1) wait_ge(&g_xz_ack[bid+1], (unsigned)(layer-1));
        // ---- rmsnorm + in_proj: 24 rows, 2 cols/thread, float4 weights ----
        {
            float* su   = sxc;
            float* srms = sxc + 320;
            const float* Wl  = in_proj_w + layer*XZW*DM;
            const float* rwl = rms_w + layer*DM;
            if (tid < SEGL*DM) su[tid] = g_h[rowbase*DM + tid];
            __syncthreads();
            if (tid < SEGL){
                float s=0.f;
                #pragma unroll
                for(int d=0;d<DM;d++){ float v=su[tid*DM+d]; s+=v*v; }
                srms[tid] = rsqrtf(s*(1.0f/DM)+1e-5f);
            }
            __syncthreads();
            float uv = 0.f;
            if (tid < SEGL*DM) uv = su[tid]*srms[tid/DM]*rwl[tid%DM];
            __syncthreads();
            if (tid < SEGL*DM) su[tid] = uv;
            __syncthreads();
            float w[2][DM];
            #pragma unroll
            for(int j=0;j<2;j++){
                const float* wp = Wl + (tid + NTH*j)*DM;
                float4 wa = __ldg((const float4*)(wp));
                float4 wb = __ldg((const float4*)(wp+4));
                float4 wc = __ldg((const float4*)(wp+8));
                w[j][0]=wa.x; w[j][1]=wa.y; w[j][2]=wa.z; w[j][3]=wa.w;
                w[j][4]=wb.x; w[j][5]=wb.y; w[j][6]=wb.z; w[j][7]=wb.w;
                w[j][8]=wc.x; w[j][9]=wc.y; w[j][10]=wc.z; w[j][11]=wc.w;
            }
            for (int r=0;r<SEGL;r++){
                float u[DM];
                #pragma unroll
                for(int d=0;d<DM;d++) u[d]=su[r*DM+d];
                #pragma unroll
                for(int j=0;j<2;j++){
                    float acc=0.f;
                    #pragma unroll
                    for(int d=0;d<DM;d++) acc += u[d]*w[j][d];
                    xzb[(rowbase+r)*XZW + tid + NTH*j] = acc;
                }
            }
        }
        signal_release(&g_xz_ready[bid]);         // = layer+1

        // ---- cvxp: needs halo rows from bid-1 ----
        if (seg_s > 0) wait_ge(&g_xz_ready[bid-1], (unsigned)(layer+1));
        {
            const int pair  = warp >> 1;
            const int split = warp & 1;
            const int r0    = pair*2;
            const int grow0 = rowbase + r0;
            const int l0    = grow0 % LP;
            const float* cwT = g_cwT + layer*4*ED;
            const float* Wx  = x_proj_w + layer*DBLW*ED;
            float part[2][DBLW];
            #pragma unroll
            for(int r=0;r<2;r++)
                #pragma unroll
                for(int t=0;t<DBLW;t++) part[r][t]=0.f;
            #pragma unroll
            for (int c=0;c<3;c++){
                int e0 = split*384 + c*128 + lane*4;
                float4 w0 = __ldg((const float4*)(cwT + 0*ED + e0));
                float4 w1 = __ldg((const float4*)(cwT + 1*ED + e0));
                float4 w2 = __ldg((const float4*)(cwT + 2*ED + e0));
                float4 b4 = __ldg((const float4*)(cwT + 3*ED + e0));
                float4 xm2 = {0,0,0,0}, xm1 = {0,0,0,0};
                if (l0>=2) xm2 = *(const float4*)(xzb + (grow0-2)*XZW + e0);
                if (l0>=1) xm1 = *(const float4*)(xzb + (grow0-1)*XZW + e0);
                float4 x0 = *(const float4*)(xzb + grow0*XZW + e0);
                float4 x1 = *(const float4*)(xzb + (grow0+1)*XZW + e0);
                float4 xc0, xc1;
                xc0.x = siluf_(b4.x + w0.x*xm2.x + w1.x*xm1.x + w2.x*x0.x);
                xc0.y = siluf_(b4.y + w0.y*xm2.y + w1.y*xm1.y + w2.y*x0.y);
                xc0.z = siluf_(b4.z + w0.z*xm2.z + w1.z*xm1.z + w2.z*x0.z);
                xc0.w = siluf_(b4.w + w0.w*xm2.w + w1.w*xm1.w + w2.w*x0.w);
                xc1.x = siluf_(b4.x + w0.x*xm1.x + w1.x*x0.x + w2.x*x1.x);
                xc1.y = siluf_(b4.y + w0.y*xm1.y + w1.y*x0.y + w2.y*x1.y);
                xc1.z = siluf_(b4.z + w0.z*xm1.z + w1.z*x0.z + w2.z*x1.z);
                xc1.w = siluf_(b4.w + w0.w*xm1.w + w1.w*x0.w + w2.w*x1.w);
                *(float4*)(sxc + r0*ED + e0)     = xc0;
                *(float4*)(sxc + (r0+1)*ED + e0) = xc1;
                #pragma unroll
                for(int t=0;t<DBLW;t++){
                    float4 wt = __ldg((const float4*)(Wx + t*ED + e0));
                    part[0][t] += wt.x*xc0.x + wt.y*xc0.y + wt.z*xc0.z + wt.w*xc0.w;
                    part[1][t] += wt.x*xc1.x + wt.y*xc1.y + wt.z*xc1.z + wt.w*xc1.w;
                }
            }
            #pragma unroll
            for(int r=0;r<2;r++)
                #pragma unroll
                for(int t=0;t<DBLW;t++){
                    float v = part[r][t];
                    for(int off=16;off>0;off>>=1) v += __shfl_down_sync(0xffffffffu, v, off);
                    if (lane==0) stmp[(split*SEGL + r0 + r)*DBLW + t] = v;
                }
        }
        __syncthreads();   // all halo loads complete
        if (tid == 0){ __threadfence(); atomicAdd(&g_xz_ack[bid], 1u); }
        for (int idx = tid; idx < SEGL*DBLW; idx += NTH){
            int row = idx / DBLW, t = idx % DBLW;
            float v = stmp[row*DBLW + t] + stmp[(SEGL+row)*DBLW + t];
            sdb[row*DBLS + (t==0 ? 16 : (t-1))] = v;
        }
        __syncthreads();
        {
            float dw = dt_proj_w[layer*ED + tid];
            float db = dt_proj_b[layer*ED + tid];
            #pragma unroll 4
            for (int r=0;r<SEGL;r++){
                float d0 = sdb[r*DBLS + 16];
                sdl[r*ED + tid] = softplusf_(d0*dw + db);
            }
        }
        __syncthreads();

        // ---- local scan (h0=0): y_local in sxc; publish (P,q) ----
        int e = tid;
        float a2[NS];
        {
            const float* ap = g_A2 + (layer*ED + e)*NS;
            #pragma unroll
            for(int n=0;n<NS;n++) a2[n]=ap[n];
        }
        bool geo = true;
        #pragma unroll
        for(int n=1;n<NS;n++)
            geo = geo && (fabsf(a2[n] - (float)(n+1)*a2[0]) <= 1e-4f*fabsf(a2[n]));
        {
            float Dv = Dp[layer*ED + e];
            float st[NS], sumd = 0.f, Pp = 1.f;
            float a20 = a2[0];
            if (geo){
                ull st2[4] = {0ull,0ull,0ull,0ull};
                float z_n = (seg_s == 0) ? xzb[rowbase*XZW + ED + e] : 0.f;
                for (int li=0; li<SEGL; li++){
                    float delta = sdl[li*ED + e];
                    float xc    = sxc[li*ED + e];
                    float dx = delta * xc;
                    ulonglong2 Bp = *(const ulonglong2*)(sdb + li*DBLS);
                    ulonglong2 Bq = *(const ulonglong2*)(sdb + li*DBLS + 4);
                    ulonglong2 Cp = *(const ulonglong2*)(sdb + li*DBLS + 8);
                    ulonglong2 Cq = *(const ulonglong2*)(sdb + li*DBLS + 12);
                    float p  = ex2f_(delta * a20);
                    Pp *= p;
                    float p2 = p*p;
                    ull da01 = pk2_(p, p2);
                    ull p22  = pk2_(p2, p2);
                    ull da23 = mul2_(da01, p22);
                    ull da45 = mul2_(da23, p22);
                    ull da67 = mul2_(da45, p22);
                    ull dx2  = pk2_(dx, dx);
                    st2[0] = fma2_(da01, st2[0], mul2_(dx2, Bp.x));
                    st2[1] = fma2_(da23, st2[1], mul2_(dx2, Bp.y));
                    st2[2] = fma2_(da45, st2[2], mul2_(dx2, Bq.x));
                    st2[3] = fma2_(da67, st2[3], mul2_(dx2, Bq.y));
                    ull y2 = pk2_(Dv*xc, 0.f);
                    y2 = fma2_(st2[0], Cp.x, y2);
                    y2 = fma2_(st2[1], Cp.y, y2);
                    y2 = fma2_(st2[2], Cq.x, y2);
                    y2 = fma2_(st2[3], Cq.y, y2);
                    float ylo, yhi; upk2_(ylo, yhi, y2);
                    float y = ylo + yhi;
                    if (seg_s == 0){
                        float z = z_n;
                        if (li < SEGL-1) z_n = xzb[(rowbase+li+1)*XZW + ED + e];
                        sxc[li*ED + e] = y * siluf_(z);
                    } else {
                        sxc[li*ED + e] = y;
                    }
                }
                #pragma unroll
                for(int k=0;k<4;k++) upk2_(st[2*k], st[2*k+1], st2[k]);
            } else {
                #pragma unroll
                for(int n=0;n<NS;n++) st[n]=0.f;
                float z_n = (seg_s == 0) ? xzb[rowbase*XZW + ED + e] : 0.f;
                for (int li=0; li<SEGL; li++){
                    float delta = sdl[li*ED + e];
                    float xc    = sxc[li*ED + e];
                    float dx = delta * xc;
                    float4 B0 = *(const float4*)(sdb + li*DBLS);
                    float4 B1 = *(const float4*)(sdb + li*DBLS + 4);
                    float4 C0 = *(const float4*)(sdb + li*DBLS + 8);
                    float4 C1 = *(const float4*)(sdb + li*DBLS + 12);
                    float Bv[NS] = {B0.x,B0.y,B0.z,B0.w,B1.x,B1.y,B1.z,B1.w};
                    float Cv[NS] = {C0.x,C0.y,C0.z,C0.w,C1.x,C1.y,C1.z,C1.w};
                    float y = Dv * xc;
                    #pragma unroll
                    for(int n=0;n<NS;n++){
                        float dan = ex2f_(delta * a2[n]);
                        st[n] = dan*st[n] + dx*Bv[n];
                        y += st[n]*Cv[n];
                    }
                    sumd += delta;
                    if (seg_s == 0){
                        float z = z_n;
                        if (li < SEGL-1) z_n = xzb[(rowbase+li+1)*XZW + ED + e];
                        sxc[li*ED + e] = y * siluf_(z);
                    } else {
                        sxc[li*ED + e] = y;
                    }
                }
            }
            if (seg_s < NSEG-1){
                if (layer >= 2) wait_ge(&g_pq_ack[bid], (unsigned)((NSEG-1-seg_s)*(layer-1)));
                int base = (layer&1)*PQSTRIDE + ((seg_s*BSZ + seg_b)*NS)*ED + e;
                if (geo){
                    float Pn = 1.f;
                    #pragma unroll
                    for(int n=0;n<NS;n++){
                        Pn *= Pp;
                        g_P[base + n*ED] = Pn;
                        g_q[base + n*ED] = st[n];
                    }
                } else {
                    #pragma unroll
                    for(int n=0;n<NS;n++){
                        g_P[base + n*ED] = ex2f_(a2[n]*sumd);
                        g_q[base + n*ED] = st[n];
                    }
                }
                signal_release(&g_pq_ready[bid]);   // = layer+1
            }
        }

        // ---- correction: y += C * cumprod(da) * h_in, gate ----
        if (seg_s > 0){
            // single merged spin over all upstream pq counters
            __syncthreads();
            if (tid == 0){
                unsigned tgt = (unsigned)(layer+1);
                for(;;){
                    bool ok = true;
                    for (int sp = 0; sp < seg_s; sp++){
                        volatile unsigned* p = (volatile unsigned*)&g_pq_ready[(seg_b<<2)|sp];
                        ok = ok && ((int)(*p - tgt) >= 0);
                    }
                    if (ok) break;
                    __nanosleep(8);
                }
                __threadfence();
            }
            __syncthreads();
            float hin[NS];
            #pragma unroll
            for(int n=0;n<NS;n++) hin[n]=0.f;
            for (int sp = 0; sp < seg_s; sp++){
                int base = (layer&1)*PQSTRIDE + ((sp*BSZ + seg_b)*NS)*ED + e;
                #pragma unroll
                for(int n=0;n<NS;n++)
                    hin[n] = g_P[base + n*ED]*hin[n] + g_q[base + n*ED];
            }
            float z_n = xzb[rowbase*XZW + ED + e];
            if (geo){
                float a20 = a2[0];
                ull hc2[4] = {pk2_(hin[0],hin[1]), pk2_(hin[2],hin[3]),
                              pk2_(hin[4],hin[5]), pk2_(hin[6],hin[7])};
                for (int li=0; li<SEGL; li++){
                    float z = z_n;
                    if (li < SEGL-1) z_n = xzb[(rowbase+li+1)*XZW + ED + e];
                    float delta = sdl[li*ED + e];
                    float p  = ex2f_(delta * a20);
                    float p2 = p*p;
                    ull da01 = pk2_(p, p2);
                    ull p22  = pk2_(p2, p2);
                    ull da23 = mul2_(da01, p22);
                    ull da45 = mul2_(da23, p22);
                    ull da67 = mul2_(da45, p22);
                    hc2[0] = mul2_(hc2[0], da01);
                    hc2[1] = mul2_(hc2[1], da23);
                    hc2[2] = mul2_(hc2[2], da45);
                    hc2[3] = mul2_(hc2[3], da67);
                    ulonglong2 Cp = *(const ulonglong2*)(sdb + li*DBLS + 8);
                    ulonglong2 Cq = *(const ulonglong2*)(sdb + li*DBLS + 12);
                    ull y2 = pk2_(sxc[li*ED + e], 0.f);
                    y2 = fma2_(hc2[0], Cp.x, y2);
                    y2 = fma2_(hc2[1], Cp.y, y2);
                    y2 = fma2_(hc2[2], Cq.x, y2);
                    y2 = fma2_(hc2[3], Cq.y, y2);
                    float ylo, yhi; upk2_(ylo, yhi, y2);
                    sxc[li*ED + e] = (ylo + yhi) * siluf_(z);
                }
            } else {
                float hc[NS];
                #pragma unroll
                for(int n=0;n<NS;n++) hc[n]=hin[n];
                for (int li=0; li<SEGL; li++){
                    float z = z_n;
                    if (li < SEGL-1) z_n = xzb[(rowbase+li+1)*XZW + ED + e];
                    float delta = sdl[li*ED + e];
                    float4 C0 = *(const float4*)(sdb + li*DBLS + 8);
                    float4 C1 = *(const float4*)(sdb + li*DBLS + 12);
                    float Cv[NS] = {C0.x,C0.y,C0.z,C0.w,C1.x,C1.y,C1.z,C1.w};
                    float y = sxc[li*ED + e];
                    #pragma unroll
                    for(int n=0;n<NS;n++){
                        hc[n] *= ex2f_(delta * a2[n]);
                        y += hc[n]*Cv[n];
                    }
                    sxc[li*ED + e] = y * siluf_(z);
                }
            }
            __syncthreads();   // g_P/g_q loads complete
            if (tid == 0){
                __threadfence();
                for (int sp = 0; sp < seg_s; sp++)
                    atomicAdd(&g_pq_ack[(seg_b<<2)|sp], 1u);
            }
        }
        __syncthreads();

        // ---- out_proj ----
        {
            const int pair  = warp >> 1;
            const int split = warp & 1;
            const int r0    = pair*2;
            const float* Wo = out_proj_w + layer*DM*ED;
            float pd[2][DM];
            #pragma unroll
            for(int r=0;r<2;r++)
                #pragma unroll
                for(int d=0;d<DM;d++) pd[r][d]=0.f;
            #pragma unroll
            for (int c=0;c<3;c++){
                int e0 = split*384 + c*128 + lane*4;
                float4 y0 = *(const float4*)(sxc + r0*ED + e0);
                float4 y1 = *(const float4*)(sxc + (r0+1)*ED + e0);
                #pragma unroll
                for(int d=0;d<DM;d++){
                    float4 wd4 = __ldg((const float4*)(Wo + d*ED + e0));
                    pd[0][d] += wd4.x*y0.x + wd4.y*y0.y + wd4.z*y0.z + wd4.w*y0.w;
                    pd[1][d] += wd4.x*y1.x + wd4.y*y1.y + wd4.z*y1.z + wd4.w*y1.w;
                }
            }
            #pragma unroll
            for(int r=0;r<2;r++)
                #pragma unroll
                for(int d=0;d<DM;d++){
                    float v = pd[r][d];
                    for(int off=16;off>0;off>>=1) v += __shfl_down_sync(0xffffffffu, v, off);
                    if (lane==0) stmp[(split*SEGL + r0 + r)*DM + d] = v;
                }
        }
        __syncthreads();
        for (int idx = tid; idx < SEGL*DM; idx += NTH){
            int row = idx / DM, d = idx % DM;
            g_h[(rowbase+row)*DM + d] += stmp[row*DM + d] + stmp[(SEGL+row)*DM + d];
        }
        __syncthreads();
    }
    gridbar();

    // ===== final: mean over L + FC + ReLU =====
    {
        float* m = sm;
        for (int b = bid; b < BSZ; b += NB){
            if (tid < DM){
                float s=0.f;
                for(int l=0;l<LP;l++) s += g_h[(b*LP+l)*DM + tid];
                m[tid]=s*(1.0f/LP);
            }
            __syncthreads();
            if (tid < EMB){
                float acc = fc_b[tid];
                #pragma unroll
                for(int d=0;d<DM;d++) acc += m[d]*fc_w[tid*DM+d];
                out[b*EMB+tid] = fmaxf(acc,0.0f);
            }
            __syncthreads();
        }
    }
}

// ---------------- launch ----------------
extern "C" void kernel_launch(void* const* d_in, const int* in_sizes, int n_in,
                              void* d_out, int out_size){
    const float* x          = (const float*)d_in[0];
    const float* conv_re_w  = (const float*)d_in[1];
    const float* conv_re_b  = (const float*)d_in[2];
    const float* conv_im_w  = (const float*)d_in[3];
    const float* conv_im_b  = (const float*)d_in[4];
    const float* pos        = (const float*)d_in[5];
    const float* bn_gamma   = (const float*)d_in[6];
    const float* bn_beta    = (const float*)d_in[7];
    const float* rms_w      = (const float*)d_in[8];
    const float* in_proj_w  = (const float*)d_in[9];
    const float* conv1d_w   = (const float*)d_in[10];
    const float* conv1d_b   = (const float*)d_in[11];
    const float* x_proj_w   = (const float*)d_in[12];
    const float* dt_proj_w  = (const float*)d_in[13];
    const float* dt_proj_b  = (const float*)d_in[14];
    const float* A_log      = (const float*)d_in[15];
    const float* Dp         = (const float*)d_in[16];
    const float* out_proj_w = (const float*)d_in[17];
    const float* fc_w       = (const float*)d_in[18];
    const float* fc_b       = (const float*)d_in[19];
    float* out = (float*)d_out;

    size_t dynbytes = (size_t)DYNF * sizeof(float);
    cudaFuncSetAttribute(k_mega, cudaFuncAttributeMaxDynamicSharedMemorySize, (int)dynbytes);

    k_mega<<<NBLK, NTH, dynbytes>>>(x, conv_re_w, conv_re_b, conv_im_w, conv_im_b, pos,
                         bn_gamma, bn_beta, rms_w, in_proj_w, conv1d_w, conv1d_b,
                         x_proj_w, dt_proj_w, dt_proj_b, A_log, Dp, out_proj_w,
                         fc_w, fc_b, out);
}

// round 16
// speedup vs baseline: 1.4960x; 1.0526x over previous
#include <cuda_runtime.h>

#define BSZ 32
#define LP 96
#define DM 12
#define ED 768
#define NS 8
#define NL 10
#define EMB 256
#define PP 50
#define ROWS (BSZ*LP)      // 3072
#define XZW (2*ED)         // 1536
#define DBLW 17
#define DBLS 20
#define NTH 768
#define NBLK 128
#define NSEG 4
#define SEGL 24
#define XZBUF (ROWS*XZW)
#define HENDSTRIDE (NBLK*NS*ED)

// smem layout (floats)
#define S_XC   0
#define S_DL   (SEGL*ED)                 // 18432
#define S_DB   (2*SEGL*ED)               // 36864
#define S_TMP  (2*SEGL*ED + SEGL*DBLS)   // 37344
#define DYNF   (S_TMP + 2*SEGL*DBLW + 32)

typedef unsigned long long ull;

// ---------------- scratch ----------------
__device__ __align__(16) float g_h[ROWS*DM];
__device__ __align__(16) float g_xz[2*XZBUF];       // layer-parity double buffer
__device__ __align__(16) float g_hend[2*HENDSTRIDE];// layer-parity final states
__device__ __align__(16) float g_A2[NL*ED*NS];
__device__ __align__(16) float g_cwT[NL*4*ED];
__device__ float g_bns[2*DM];
__device__ unsigned g_xz_ready[NBLK];
__device__ unsigned g_xz_ack[NBLK];
__device__ unsigned g_he_ready[NBLK];
__device__ unsigned g_he_ack[NBLK];
__device__ volatile unsigned g_bar_gen;
__device__ unsigned g_bar_cnt;

// ---------------- fast math ----------------
__device__ __forceinline__ float ex2f_(float x){ float y; asm("ex2.approx.f32 %0, %1;":"=f"(y):"f"(x)); return y; }
__device__ __forceinline__ float lg2f_(float x){ float y; asm("lg2.approx.f32 %0, %1;":"=f"(y):"f"(x)); return y; }
__device__ __forceinline__ float rcpf_(float x){ float y; asm("rcp.approx.f32 %0, %1;":"=f"(y):"f"(x)); return y; }
#define L2E 1.4426950408889634f
#define LN2 0.6931471805599453f
__device__ __forceinline__ float sigmoidf_(float x){ return rcpf_(1.0f + ex2f_(-x*L2E)); }
__device__ __forceinline__ float siluf_(float x){ return x * sigmoidf_(x); }
__device__ __forceinline__ float softplusf_(float x){
    return (x > 20.0f) ? x : LN2*lg2f_(1.0f + ex2f_(x*L2E));
}
// packed f32x2 helpers
__device__ __forceinline__ ull pk2_(float lo, float hi){ ull v; asm("mov.b64 %0, {%1,%2};" : "=l"(v) : "f"(lo), "f"(hi)); return v; }
__device__ __forceinline__ void upk2_(float& lo, float& hi, ull v){ asm("mov.b64 {%0,%1}, %2;" : "=f"(lo), "=f"(hi) : "l"(v)); }
__device__ __forceinline__ ull mul2_(ull a, ull b){ ull d; asm("mul.rn.f32x2 %0, %1, %2;" : "=l"(d) : "l"(a), "l"(b)); return d; }
__device__ __forceinline__ ull fma2_(ull a, ull b, ull c){ ull d; asm("fma.rn.f32x2 %0, %1, %2, %3;" : "=l"(d) : "l"(a), "l"(b), "l"(c)); return d; }

// ---------------- sync primitives ----------------
__device__ __forceinline__ void gridbar(){
    __threadfence();
    __syncthreads();
    if (threadIdx.x == 0){
        unsigned gen = g_bar_gen;
        unsigned old = atomicAdd(&g_bar_cnt, 1u);
        if (old == gridDim.x - 1u){
            g_bar_cnt = 0u;
            __threadfence();
            g_bar_gen = gen + 1u;
        } else {
            while (g_bar_gen == gen) __nanosleep(20);
        }
        __threadfence();
    }
    __syncthreads();
}
__device__ __forceinline__ void wait_ge(unsigned* ctr, unsigned target){
    __syncthreads();
    if (threadIdx.x == 0){
        volatile unsigned* p = (volatile unsigned*)ctr;
        unsigned v = *p;
        while ((int)(v - target) < 0){ __nanosleep(8); v = *p; }
        __threadfence();   // acquire
    }
    __syncthreads();
}
__device__ __forceinline__ void signal_release(unsigned* ctr){
    __threadfence();
    __syncthreads();
    if (threadIdx.x == 0) atomicAdd(ctr, 1u);
}

// ---------------- megakernel ----------------
__global__ void __launch_bounds__(NTH,1) k_mega(
    const float* __restrict__ x,
    const float* __restrict__ conv_re_w, const float* __restrict__ conv_re_b,
    const float* __restrict__ conv_im_w, const float* __restrict__ conv_im_b,
    const float* __restrict__ pos,
    const float* __restrict__ bn_gamma, const float* __restrict__ bn_beta,
    const float* __restrict__ rms_w,
    const float* __restrict__ in_proj_w,
    const float* __restrict__ conv1d_w, const float* __restrict__ conv1d_b,
    const float* __restrict__ x_proj_w,
    const float* __restrict__ dt_proj_w, const float* __restrict__ dt_proj_b,
    const float* __restrict__ A_log,  const float* __restrict__ Dp,
    const float* __restrict__ out_proj_w,
    const float* __restrict__ fc_w, const float* __restrict__ fc_b,
    float* __restrict__ out)
{
    extern __shared__ float sm[];
    float* sxc  = sm + S_XC;
    float* sdl  = sm + S_DL;
    float* sdb  = sm + S_DB;
    float* stmp = sm + S_TMP;
    const int NB  = gridDim.x;
    const int bid = blockIdx.x;
    const int tid = threadIdx.x;
    const int gsz = NB*NTH;
    const int gtid = bid*NTH + tid;
    const int warp = tid >> 5, lane = tid & 31;

    const int seg_b = bid >> 2;            // batch
    const int seg_s = bid & 3;             // quarter
    const int rowbase = bid*SEGL;

    // ===== phase 0 =====
    if (tid == 0){
        g_xz_ready[bid]=0u; g_xz_ack[bid]=0u;
        g_he_ready[bid]=0u; g_he_ack[bid]=0u;
    }
    for (int i = gtid; i < NL*ED*NS; i += gsz) g_A2[i] = -expf(A_log[i]) * L2E;
    for (int i = gtid; i < NL*ED; i += gsz){
        int layer = i / ED, e = i % ED;
        const float* wp = conv1d_w + i*3;
        float* dst = g_cwT + layer*4*ED;
        dst[0*ED+e] = wp[0];
        dst[1*ED+e] = wp[1];
        dst[2*ED+e] = wp[2];
        dst[3*ED+e] = conv1d_b[i];
    }
    if (gtid < 2*DM) g_bns[gtid] = 0.f;
    for (int idx = gtid; idx < ROWS*DM; idx += gsz){
        int row = idx / DM, o = idx % DM;
        int b = row / LP, l = row % LP;
        const float* xr = x + b*(2*LP*PP) + l*PP;
        const float* xi = xr + LP*PP;
        float acc;
        if (o < 6){
            acc = conv_re_b[o] - conv_im_b[o];
            const float* w1 = conv_re_w + o*PP; const float* w2 = conv_im_w + o*PP;
            #pragma unroll 10
            for (int k=0;k<PP;k++) acc += xr[k]*w1[k] - xi[k]*w2[k];
        } else {
            int o6 = o-6;
            acc = conv_re_b[o6] + conv_im_b[o6];
            const float* w1 = conv_re_w + o6*PP; const float* w2 = conv_im_w + o6*PP;
            #pragma unroll 10
            for (int k=0;k<PP;k++) acc += xi[k]*w1[k] + xr[k]*w2[k];
        }
        g_h[idx] = acc + pos[l*DM + o];
    }
    gridbar();

    // ===== BN sums =====
    {
        float ls[DM], lq[DM];
        #pragma unroll
        for(int c=0;c<DM;c++){ ls[c]=0.f; lq[c]=0.f; }
        for (int j = gtid; j < ROWS; j += gsz){
            #pragma unroll
            for(int c=0;c<DM;c++){ float v=g_h[j*DM+c]; ls[c]+=v; lq[c]+=v*v; }
        }
        #pragma unroll
        for(int c=0;c<DM;c++){
            float a=ls[c], q=lq[c];
            for(int off=16;off>0;off>>=1){
                a+=__shfl_down_sync(0xffffffffu,a,off);
                q+=__shfl_down_sync(0xffffffffu,q,off);
            }
            if (lane==0 && (a!=0.f || q!=0.f)){
                atomicAdd(&g_bns[c], a);
                atomicAdd(&g_bns[DM+c], q);
            }
        }
    }
    gridbar();

    // ===== BN apply + silu =====
    {
        if (tid < DM){
            float mu  = g_bns[tid]*(1.0f/ROWS);
            float var = g_bns[DM+tid]*(1.0f/ROWS) - mu*mu;
            float sc  = rsqrtf(var+1e-6f)*bn_gamma[tid];
            sm[tid]    = sc;
            sm[DM+tid] = bn_beta[tid] - mu*sc;
        }
        __syncthreads();
        for (int idx = gtid; idx < ROWS*DM; idx += gsz){
            int c = idx % DM;
            float v = g_h[idx]*sm[c] + sm[DM+c];
            g_h[idx] = siluf_(v);
        }
        __syncthreads();
    }
    gridbar();

    // ===== layers (pipelined; no grid barriers) =====
    for (int layer = 0; layer < NL; layer++){
        float* xzb = g_xz + (layer&1)*XZBUF;
        if (layer >= 2 && seg_s < NSEG-1) wait_ge(&g_xz_ack[bid+1], (unsigned)(layer-1));
        // ---- rmsnorm + in_proj ----
        {
            float* su   = sxc;
            float* srms = sxc + 320;
            const float* Wl  = in_proj_w + layer*XZW*DM;
            const float* rwl = rms_w + layer*DM;
            if (tid < SEGL*DM) su[tid] = g_h[rowbase*DM + tid];
            __syncthreads();
            if (tid < SEGL){
                float s=0.f;
                #pragma unroll
                for(int d=0;d<DM;d++){ float v=su[tid*DM+d]; s+=v*v; }
                srms[tid] = rsqrtf(s*(1.0f/DM)+1e-5f);
            }
            __syncthreads();
            float uv = 0.f;
            if (tid < SEGL*DM) uv = su[tid]*srms[tid/DM]*rwl[tid%DM];
            __syncthreads();
            if (tid < SEGL*DM) su[tid] = uv;
            __syncthreads();
            float w[2][DM];
            #pragma unroll
            for(int j=0;j<2;j++){
                const float* wp = Wl + (tid + NTH*j)*DM;
                float4 wa = __ldg((const float4*)(wp));
                float4 wb = __ldg((const float4*)(wp+4));
                float4 wc = __ldg((const float4*)(wp+8));
                w[j][0]=wa.x; w[j][1]=wa.y; w[j][2]=wa.z; w[j][3]=wa.w;
                w[j][4]=wb.x; w[j][5]=wb.y; w[j][6]=wb.z; w[j][7]=wb.w;
                w[j][8]=wc.x; w[j][9]=wc.y; w[j][10]=wc.z; w[j][11]=wc.w;
            }
            for (int r=0;r<SEGL;r++){
                float u[DM];
                #pragma unroll
                for(int d=0;d<DM;d++) u[d]=su[r*DM+d];
                #pragma unroll
                for(int j=0;j<2;j++){
                    float acc=0.f;
                    #pragma unroll
                    for(int d=0;d<DM;d++) acc += u[d]*w[j][d];
                    xzb[(rowbase+r)*XZW + tid + NTH*j] = acc;
                }
            }
        }
        signal_release(&g_xz_ready[bid]);         // = layer+1

        // ---- cvxp: needs halo rows from bid-1 ----
        if (seg_s > 0) wait_ge(&g_xz_ready[bid-1], (unsigned)(layer+1));
        {
            const int pair  = warp >> 1;
            const int split = warp & 1;
            const int r0    = pair*2;
            const int grow0 = rowbase + r0;
            const int l0    = grow0 % LP;
            const float* cwT = g_cwT + layer*4*ED;
            const float* Wx  = x_proj_w + layer*DBLW*ED;
            float part[2][DBLW];
            #pragma unroll
            for(int r=0;r<2;r++)
                #pragma unroll
                for(int t=0;t<DBLW;t++) part[r][t]=0.f;
            #pragma unroll
            for (int c=0;c<3;c++){
                int e0 = split*384 + c*128 + lane*4;
                float4 w0 = __ldg((const float4*)(cwT + 0*ED + e0));
                float4 w1 = __ldg((const float4*)(cwT + 1*ED + e0));
                float4 w2 = __ldg((const float4*)(cwT + 2*ED + e0));
                float4 b4 = __ldg((const float4*)(cwT + 3*ED + e0));
                float4 xm2 = {0,0,0,0}, xm1 = {0,0,0,0};
                if (l0>=2) xm2 = *(const float4*)(xzb + (grow0-2)*XZW + e0);
                if (l0>=1) xm1 = *(const float4*)(xzb + (grow0-1)*XZW + e0);
                float4 x0 = *(const float4*)(xzb + grow0*XZW + e0);
                float4 x1 = *(const float4*)(xzb + (grow0+1)*XZW + e0);
                float4 xc0, xc1;
                xc0.x = siluf_(b4.x + w0.x*xm2.x + w1.x*xm1.x + w2.x*x0.x);
                xc0.y = siluf_(b4.y + w0.y*xm2.y + w1.y*xm1.y + w2.y*x0.y);
                xc0.z = siluf_(b4.z + w0.z*xm2.z + w1.z*xm1.z + w2.z*x0.z);
                xc0.w = siluf_(b4.w + w0.w*xm2.w + w1.w*x0.w*0.f + w2.w*x0.w + w1.w*xm1.w);
                // (re-expressed below correctly; keep simple form)
                xc0.w = siluf_(b4.w + w0.w*xm2.w + w1.w*xm1.w + w2.w*x0.w);
                xc1.x = siluf_(b4.x + w0.x*xm1.x + w1.x*x0.x + w2.x*x1.x);
                xc1.y = siluf_(b4.y + w0.y*xm1.y + w1.y*x0.y + w2.y*x1.y);
                xc1.z = siluf_(b4.z + w0.z*xm1.z + w1.z*x0.z + w2.z*x1.z);
                xc1.w = siluf_(b4.w + w0.w*xm1.w + w1.w*x0.w + w2.w*x1.w);
                *(float4*)(sxc + r0*ED + e0)     = xc0;
                *(float4*)(sxc + (r0+1)*ED + e0) = xc1;
                #pragma unroll
                for(int t=0;t<DBLW;t++){
                    float4 wt = __ldg((const float4*)(Wx + t*ED + e0));
                    part[0][t] += wt.x*xc0.x + wt.y*xc0.y + wt.z*xc0.z + wt.w*xc0.w;
                    part[1][t] += wt.x*xc1.x + wt.y*xc1.y + wt.z*xc1.z + wt.w*xc1.w;
                }
            }
            #pragma unroll
            for(int r=0;r<2;r++)
                #pragma unroll
                for(int t=0;t<DBLW;t++){
                    float v = part[r][t];
                    for(int off=16;off>0;off>>=1) v += __shfl_down_sync(0xffffffffu, v, off);
                    if (lane==0) stmp[(split*SEGL + r0 + r)*DBLW + t] = v;
                }
        }
        __syncthreads();
        if (tid == 0){ __threadfence(); atomicAdd(&g_xz_ack[bid], 1u); }
        for (int idx = tid; idx < SEGL*DBLW; idx += NTH){
            int row = idx / DBLW, t = idx % DBLW;
            float v = stmp[row*DBLW + t] + stmp[(SEGL+row)*DBLW + t];
            sdb[row*DBLS + (t==0 ? 16 : (t-1))] = v;
        }
        __syncthreads();
        {
            float dw = dt_proj_w[layer*ED + tid];
            float db = dt_proj_b[layer*ED + tid];
            #pragma unroll 4
            for (int r=0;r<SEGL;r++){
                float d0 = sdb[r*DBLS + 16];
                sdl[r*ED + tid] = softplusf_(d0*dw + db);
            }
        }
        __syncthreads();

        // ---- chain scan: exact state handoff between segments ----
        int e = tid;
        float a2[NS];
        {
            const float* ap = g_A2 + (layer*ED + e)*NS;
            #pragma unroll
            for(int n=0;n<NS;n++) a2[n]=ap[n];
        }
        bool geo = true;
        #pragma unroll
        for(int n=1;n<NS;n++)
            geo = geo && (fabsf(a2[n] - (float)(n+1)*a2[0]) <= 1e-4f*fabsf(a2[n]));

        float hin[NS];
        if (seg_s > 0){
            wait_ge(&g_he_ready[bid-1], (unsigned)(layer+1));
            const float* hb = g_hend + (layer&1)*HENDSTRIDE + (bid-1)*NS*ED + e;
            #pragma unroll
            for(int n=0;n<NS;n++) hin[n] = hb[n*ED];
            __syncthreads();   // all loads done
            if (tid == 0){ __threadfence(); atomicAdd(&g_he_ack[bid-1], 1u); }
        } else {
            #pragma unroll
            for(int n=0;n<NS;n++) hin[n] = 0.f;
        }
        {
            float Dv = Dp[layer*ED + e];
            float st[NS];
            float a20 = a2[0];
            if (geo){
                ull st2[4] = {pk2_(hin[0],hin[1]), pk2_(hin[2],hin[3]),
                              pk2_(hin[4],hin[5]), pk2_(hin[6],hin[7])};
                float z_n = xzb[rowbase*XZW + ED + e];
                for (int li=0; li<SEGL; li++){
                    float z = z_n;
                    if (li < SEGL-1) z_n = xzb[(rowbase+li+1)*XZW + ED + e];
                    float delta = sdl[li*ED + e];
                    float xc    = sxc[li*ED + e];
                    float dx = delta * xc;
                    ulonglong2 Bp = *(const ulonglong2*)(sdb + li*DBLS);
                    ulonglong2 Bq = *(const ulonglong2*)(sdb + li*DBLS + 4);
                    ulonglong2 Cp = *(const ulonglong2*)(sdb + li*DBLS + 8);
                    ulonglong2 Cq = *(const ulonglong2*)(sdb + li*DBLS + 12);
                    float p  = ex2f_(delta * a20);
                    float p2 = p*p;
                    ull da01 = pk2_(p, p2);
                    ull p22  = pk2_(p2, p2);
                    ull da23 = mul2_(da01, p22);
                    ull da45 = mul2_(da23, p22);
                    ull da67 = mul2_(da45, p22);
                    ull dx2  = pk2_(dx, dx);
                    st2[0] = fma2_(da01, st2[0], mul2_(dx2, Bp.x));
                    st2[1] = fma2_(da23, st2[1], mul2_(dx2, Bp.y));
                    st2[2] = fma2_(da45, st2[2], mul2_(dx2, Bq.x));
                    st2[3] = fma2_(da67, st2[3], mul2_(dx2, Bq.y));
                    ull y2 = pk2_(Dv*xc, 0.f);
                    y2 = fma2_(st2[0], Cp.x, y2);
                    y2 = fma2_(st2[1], Cp.y, y2);
                    y2 = fma2_(st2[2], Cq.x, y2);
                    y2 = fma2_(st2[3], Cq.y, y2);
                    float ylo, yhi; upk2_(ylo, yhi, y2);
                    sxc[li*ED + e] = (ylo + yhi) * siluf_(z);
                }
                #pragma unroll
                for(int k=0;k<4;k++) upk2_(st[2*k], st[2*k+1], st2[k]);
            } else {
                #pragma unroll
                for(int n=0;n<NS;n++) st[n]=hin[n];
                float z_n = xzb[rowbase*XZW + ED + e];
                for (int li=0; li<SEGL; li++){
                    float z = z_n;
                    if (li < SEGL-1) z_n = xzb[(rowbase+li+1)*XZW + ED + e];
                    float delta = sdl[li*ED + e];
                    float xc    = sxc[li*ED + e];
                    float dx = delta * xc;
                    float4 B0 = *(const float4*)(sdb + li*DBLS);
                    float4 B1 = *(const float4*)(sdb + li*DBLS + 4);
                    float4 C0 = *(const float4*)(sdb + li*DBLS + 8);
                    float4 C1 = *(const float4*)(sdb + li*DBLS + 12);
                    float Bv[NS] = {B0.x,B0.y,B0.z,B0.w,B1.x,B1.y,B1.z,B1.w};
                    float Cv[NS] = {C0.x,C0.y,C0.z,C0.w,C1.x,C1.y,C1.z,C1.w};
                    float y = Dv * xc;
                    #pragma unroll
                    for(int n=0;n<NS;n++){
                        float dan = ex2f_(delta * a2[n]);
                        st[n] = dan*st[n] + dx*Bv[n];
                        y += st[n]*Cv[n];
                    }
                    sxc[li*ED + e] = y * siluf_(z);
                }
            }
            if (seg_s < NSEG-1){
                if (layer >= 2) wait_ge(&g_he_ack[bid], (unsigned)(layer-1));
                float* hb = g_hend + (layer&1)*HENDSTRIDE + bid*NS*ED + e;
                #pragma unroll
                for(int n=0;n<NS;n++) hb[n*ED] = st[n];
                signal_release(&g_he_ready[bid]);   // = layer+1
            }
        }
        __syncthreads();

        // ---- out_proj ----
        {
            const int pair  = warp >> 1;
            const int split = warp & 1;
            const int r0    = pair*2;
            const float* Wo = out_proj_w + layer*DM*ED;
            float pd[2][DM];
            #pragma unroll
            for(int r=0;r<2;r++)
                #pragma unroll
                for(int d=0;d<DM;d++) pd[r][d]=0.f;
            #pragma unroll
            for (int c=0;c<3;c++){
                int e0 = split*384 + c*128 + lane*4;
                float4 y0 = *(const float4*)(sxc + r0*ED + e0);
                float4 y1 = *(const float4*)(sxc + (r0+1)*ED + e0);
                #pragma unroll
                for(int d=0;d<DM;d++){
                    float4 wd4 = __ldg((const float4*)(Wo + d*ED + e0));
                    pd[0][d] += wd4.x*y0.x + wd4.y*y0.y + wd4.z*y0.z + wd4.w*y0.w;
                    pd[1][d] += wd4.x*y1.x + wd4.y*y1.y + wd4.z*y1.z + wd4.w*y1.w;
                }
            }
            #pragma unroll
            for(int r=0;r<2;r++)
                #pragma unroll
                for(int d=0;d<DM;d++){
                    float v = pd[r][d];
                    for(int off=16;off>0;off>>=1) v += __shfl_down_sync(0xffffffffu, v, off);
                    if (lane==0) stmp[(split*SEGL + r0 + r)*DM + d] = v;
                }
        }
        __syncthreads();
        for (int idx = tid; idx < SEGL*DM; idx += NTH){
            int row = idx / DM, d = idx % DM;
            g_h[(rowbase+row)*DM + d] += stmp[row*DM + d] + stmp[(SEGL+row)*DM + d];
        }
        __syncthreads();
    }
    gridbar();

    // ===== final: mean over L + FC + ReLU =====
    {
        float* m = sm;
        for (int b = bid; b < BSZ; b += NB){
            if (tid < DM){
                float s=0.f;
                for(int l=0;l<LP;l++) s += g_h[(b*LP+l)*DM + tid];
                m[tid]=s*(1.0f/LP);
            }
            __syncthreads();
            if (tid < EMB){
                float acc = fc_b[tid];
                #pragma unroll
                for(int d=0;d<DM;d++) acc += m[d]*fc_w[tid*DM+d];
                out[b*EMB+tid] = fmaxf(acc,0.0f);
            }
            __syncthreads();
        }
    }
}

// ---------------- launch ----------------
extern "C" void kernel_launch(void* const* d_in, const int* in_sizes, int n_in,
                              void* d_out, int out_size){
    const float* x          = (const float*)d_in[0];
    const float* conv_re_w  = (const float*)d_in[1];
    const float* conv_re_b  = (const float*)d_in[2];
    const float* conv_im_w  = (const float*)d_in[3];
    const float* conv_im_b  = (const float*)d_in[4];
    const float* pos        = (const float*)d_in[5];
    const float* bn_gamma   = (const float*)d_in[6];
    const float* bn_beta    = (const float*)d_in[7];
    const float* rms_w      = (const float*)d_in[8];
    const float* in_proj_w  = (const float*)d_in[9];
    const float* conv1d_w   = (const float*)d_in[10];
    const float* conv1d_b   = (const float*)d_in[11];
    const float* x_proj_w   = (const float*)d_in[12];
    const float* dt_proj_w  = (const float*)d_in[13];
    const float* dt_proj_b  = (const float*)d_in[14];
    const float* A_log      = (const float*)d_in[15];
    const float* Dp         = (const float*)d_in[16];
    const float* out_proj_w = (const float*)d_in[17];
    const float* fc_w       = (const float*)d_in[18];
    const float* fc_b       = (const float*)d_in[19];
    float* out = (float*)d_out;

    size_t dynbytes = (size_t)DYNF * sizeof(float);
    cudaFuncSetAttribute(k_mega, cudaFuncAttributeMaxDynamicSharedMemorySize, (int)dynbytes);

    k_mega<<<NBLK, NTH, dynbytes>>>(x, conv_re_w, conv_re_b, conv_im_w, conv_im_b, pos,
                         bn_gamma, bn_beta, rms_w, in_proj_w, conv1d_w, conv1d_b,
                         x_proj_w, dt_proj_w, dt_proj_b, A_log, Dp, out_proj_w,
                         fc_w, fc_b, out);
}

// round 17
// speedup vs baseline: 1.5201x; 1.0161x over previous
#include <cuda_runtime.h>

#define BSZ 32
#define LP 96
#define DM 12
#define ED 768
#define NS 8
#define NL 10
#define EMB 256
#define PP 50
#define ROWS (BSZ*LP)      // 3072
#define XZW (2*ED)         // 1536
#define DBLW 17
#define DBLS 20
#define NTH 768
#define NBLK 128
#define NSEG 4
#define SEGL 24
#define XZBUF (ROWS*XZW)
#define HENDSTRIDE (NBLK*NS*ED)

// smem layout (floats)
#define S_XC   0
#define S_DL   (SEGL*ED)                 // 18432
#define S_DB   (2*SEGL*ED)               // 36864
#define S_TMP  (2*SEGL*ED + SEGL*DBLS)   // 37344
#define S_RES  (S_TMP + 2*SEGL*DBLW)     // 38160
#define DYNF   (S_RES + SEGL*DM + 32)

typedef unsigned long long ull;

// ---------------- scratch ----------------
__device__ __align__(16) float g_h[ROWS*DM];
__device__ __align__(16) float g_xz[2*XZBUF];       // layer-parity double buffer
__device__ __align__(16) float g_hend[2*HENDSTRIDE];// layer-parity final states
__device__ __align__(16) float g_A2[NL*ED*NS];
__device__ __align__(16) float g_cwT[NL*4*ED];
__device__ float g_bns[2*DM];
__device__ unsigned g_xz_ready[NBLK];
__device__ unsigned g_xz_ack[NBLK];
__device__ unsigned g_he_ready[NBLK];
__device__ unsigned g_he_ack[NBLK];
__device__ volatile unsigned g_bar_gen;
__device__ unsigned g_bar_cnt;

// ---------------- fast math ----------------
__device__ __forceinline__ float ex2f_(float x){ float y; asm("ex2.approx.f32 %0, %1;":"=f"(y):"f"(x)); return y; }
__device__ __forceinline__ float lg2f_(float x){ float y; asm("lg2.approx.f32 %0, %1;":"=f"(y):"f"(x)); return y; }
__device__ __forceinline__ float rcpf_(float x){ float y; asm("rcp.approx.f32 %0, %1;":"=f"(y):"f"(x)); return y; }
#define L2E 1.4426950408889634f
#define LN2 0.6931471805599453f
__device__ __forceinline__ float sigmoidf_(float x){ return rcpf_(1.0f + ex2f_(-x*L2E)); }
__device__ __forceinline__ float siluf_(float x){ return x * sigmoidf_(x); }
__device__ __forceinline__ float softplusf_(float x){
    return (x > 20.0f) ? x : LN2*lg2f_(1.0f + ex2f_(x*L2E));
}
// packed f32x2 helpers
__device__ __forceinline__ ull pk2_(float lo, float hi){ ull v; asm("mov.b64 %0, {%1,%2};" : "=l"(v) : "f"(lo), "f"(hi)); return v; }
__device__ __forceinline__ void upk2_(float& lo, float& hi, ull v){ asm("mov.b64 {%0,%1}, %2;" : "=f"(lo), "=f"(hi) : "l"(v)); }
__device__ __forceinline__ ull mul2_(ull a, ull b){ ull d; asm("mul.rn.f32x2 %0, %1, %2;" : "=l"(d) : "l"(a), "l"(b)); return d; }
__device__ __forceinline__ ull fma2_(ull a, ull b, ull c){ ull d; asm("fma.rn.f32x2 %0, %1, %2, %3;" : "=l"(d) : "l"(a), "l"(b), "l"(c)); return d; }

// ---------------- sync primitives ----------------
__device__ __forceinline__ void gridbar(){
    __threadfence();
    __syncthreads();
    if (threadIdx.x == 0){
        unsigned gen = g_bar_gen;
        unsigned old = atomicAdd(&g_bar_cnt, 1u);
        if (old == gridDim.x - 1u){
            g_bar_cnt = 0u;
            __threadfence();
            g_bar_gen = gen + 1u;
        } else {
            while (g_bar_gen == gen) __nanosleep(20);
        }
        __threadfence();
    }
    __syncthreads();
}
__device__ __forceinline__ void wait_ge(unsigned* ctr, unsigned target){
    __syncthreads();
    if (threadIdx.x == 0){
        volatile unsigned* p = (volatile unsigned*)ctr;
        unsigned v = *p;
        while ((int)(v - target) < 0){ __nanosleep(8); v = *p; }
        __threadfence();   // acquire
    }
    __syncthreads();
}
__device__ __forceinline__ void signal_release(unsigned* ctr){
    __threadfence();
    __syncthreads();
    if (threadIdx.x == 0) atomicAdd(ctr, 1u);
}

// ---------------- megakernel ----------------
__global__ void __launch_bounds__(NTH,1) k_mega(
    const float* __restrict__ x,
    const float* __restrict__ conv_re_w, const float* __restrict__ conv_re_b,
    const float* __restrict__ conv_im_w, const float* __restrict__ conv_im_b,
    const float* __restrict__ pos,
    const float* __restrict__ bn_gamma, const float* __restrict__ bn_beta,
    const float* __restrict__ rms_w,
    const float* __restrict__ in_proj_w,
    const float* __restrict__ conv1d_w, const float* __restrict__ conv1d_b,
    const float* __restrict__ x_proj_w,
    const float* __restrict__ dt_proj_w, const float* __restrict__ dt_proj_b,
    const float* __restrict__ A_log,  const float* __restrict__ Dp,
    const float* __restrict__ out_proj_w,
    const float* __restrict__ fc_w, const float* __restrict__ fc_b,
    float* __restrict__ out)
{
    extern __shared__ float sm[];
    float* sxc  = sm + S_XC;
    float* sdl  = sm + S_DL;
    float* sdb  = sm + S_DB;
    float* stmp = sm + S_TMP;
    float* sres = sm + S_RES;
    const int NB  = gridDim.x;
    const int bid = blockIdx.x;
    const int tid = threadIdx.x;
    const int gsz = NB*NTH;
    const int gtid = bid*NTH + tid;
    const int warp = tid >> 5, lane = tid & 31;

    const int seg_s = bid & 3;             // quarter
    const int rowbase = bid*SEGL;

    // ===== phase 0 =====
    if (tid == 0){
        g_xz_ready[bid]=0u; g_xz_ack[bid]=0u;
        g_he_ready[bid]=0u; g_he_ack[bid]=0u;
    }
    for (int i = gtid; i < NL*ED*NS; i += gsz) g_A2[i] = -expf(A_log[i]) * L2E;
    for (int i = gtid; i < NL*ED; i += gsz){
        int layer = i / ED, e = i % ED;
        const float* wp = conv1d_w + i*3;
        float* dst = g_cwT + layer*4*ED;
        dst[0*ED+e] = wp[0];
        dst[1*ED+e] = wp[1];
        dst[2*ED+e] = wp[2];
        dst[3*ED+e] = conv1d_b[i];
    }
    if (gtid < 2*DM) g_bns[gtid] = 0.f;
    for (int idx = gtid; idx < ROWS*DM; idx += gsz){
        int row = idx / DM, o = idx % DM;
        int b = row / LP, l = row % LP;
        const float* xr = x + b*(2*LP*PP) + l*PP;
        const float* xi = xr + LP*PP;
        float acc;
        if (o < 6){
            acc = conv_re_b[o] - conv_im_b[o];
            const float* w1 = conv_re_w + o*PP; const float* w2 = conv_im_w + o*PP;
            #pragma unroll 10
            for (int k=0;k<PP;k++) acc += xr[k]*w1[k] - xi[k]*w2[k];
        } else {
            int o6 = o-6;
            acc = conv_re_b[o6] + conv_im_b[o6];
            const float* w1 = conv_re_w + o6*PP; const float* w2 = conv_im_w + o6*PP;
            #pragma unroll 10
            for (int k=0;k<PP;k++) acc += xi[k]*w1[k] + xr[k]*w2[k];
        }
        g_h[idx] = acc + pos[l*DM + o];
    }
    gridbar();

    // ===== BN sums =====
    {
        float ls[DM], lq[DM];
        #pragma unroll
        for(int c=0;c<DM;c++){ ls[c]=0.f; lq[c]=0.f; }
        for (int j = gtid; j < ROWS; j += gsz){
            #pragma unroll
            for(int c=0;c<DM;c++){ float v=g_h[j*DM+c]; ls[c]+=v; lq[c]+=v*v; }
        }
        #pragma unroll
        for(int c=0;c<DM;c++){
            float a=ls[c], q=lq[c];
            for(int off=16;off>0;off>>=1){
                a+=__shfl_down_sync(0xffffffffu,a,off);
                q+=__shfl_down_sync(0xffffffffu,q,off);
            }
            if (lane==0 && (a!=0.f || q!=0.f)){
                atomicAdd(&g_bns[c], a);
                atomicAdd(&g_bns[DM+c], q);
            }
        }
    }
    gridbar();

    // ===== BN apply + silu =====
    {
        if (tid < DM){
            float mu  = g_bns[tid]*(1.0f/ROWS);
            float var = g_bns[DM+tid]*(1.0f/ROWS) - mu*mu;
            float sc  = rsqrtf(var+1e-6f)*bn_gamma[tid];
            sm[tid]    = sc;
            sm[DM+tid] = bn_beta[tid] - mu*sc;
        }
        __syncthreads();
        for (int idx = gtid; idx < ROWS*DM; idx += gsz){
            int c = idx % DM;
            float v = g_h[idx]*sm[c] + sm[DM+c];
            g_h[idx] = siluf_(v);
        }
        __syncthreads();
    }
    gridbar();

    // ===== load residual segment into smem (block-private for all layers) =====
    if (tid < SEGL*DM) sres[tid] = g_h[rowbase*DM + tid];
    __syncthreads();

    // ===== layers (pipelined; no grid barriers) =====
    for (int layer = 0; layer < NL; layer++){
        float* xzb = g_xz + (layer&1)*XZBUF;
        if (layer >= 2 && seg_s < NSEG-1) wait_ge(&g_xz_ack[bid+1], (unsigned)(layer-1));
        // ---- rmsnorm + in_proj (rms_w folded into weights; rows 22-23 first) ----
        float w[2][DM];
        {
            float* su   = sxc;
            float* srms = sxc + 320;
            const float* Wl  = in_proj_w + layer*XZW*DM;
            const float* rwl = rms_w + layer*DM;
            float rw[DM];
            #pragma unroll
            for(int d=0;d<DM;d++) rw[d] = __ldg(rwl + d);
            #pragma unroll
            for(int j=0;j<2;j++){
                const float* wp = Wl + (tid + NTH*j)*DM;
                float4 wa = __ldg((const float4*)(wp));
                float4 wb = __ldg((const float4*)(wp+4));
                float4 wc = __ldg((const float4*)(wp+8));
                w[j][0]=wa.x*rw[0]; w[j][1]=wa.y*rw[1]; w[j][2]=wa.z*rw[2]; w[j][3]=wa.w*rw[3];
                w[j][4]=wb.x*rw[4]; w[j][5]=wb.y*rw[5]; w[j][6]=wb.z*rw[6]; w[j][7]=wb.w*rw[7];
                w[j][8]=wc.x*rw[8]; w[j][9]=wc.y*rw[9]; w[j][10]=wc.z*rw[10]; w[j][11]=wc.w*rw[11];
            }
            if (tid < SEGL*DM) su[tid] = sres[tid];
            __syncthreads();
            if (tid < SEGL){
                float s=0.f;
                #pragma unroll
                for(int d=0;d<DM;d++){ float v=su[tid*DM+d]; s+=v*v; }
                srms[tid] = rsqrtf(s*(1.0f/DM)+1e-5f);
            }
            __syncthreads();
            // halo rows first
            #pragma unroll
            for (int r=SEGL-2;r<SEGL;r++){
                float u[DM];
                #pragma unroll
                for(int d=0;d<DM;d++) u[d]=su[r*DM+d];
                float rm = srms[r];
                #pragma unroll
                for(int j=0;j<2;j++){
                    float acc=0.f;
                    #pragma unroll
                    for(int d=0;d<DM;d++) acc += u[d]*w[j][d];
                    xzb[(rowbase+r)*XZW + tid + NTH*j] = acc*rm;
                }
            }
        }
        signal_release(&g_xz_ready[bid]);         // = layer+1 (guards rows 22-23)
        {
            float* su   = sxc;
            float* srms = sxc + 320;
            for (int r=0;r<SEGL-2;r++){
                float u[DM];
                #pragma unroll
                for(int d=0;d<DM;d++) u[d]=su[r*DM+d];
                float rm = srms[r];
                #pragma unroll
                for(int j=0;j<2;j++){
                    float acc=0.f;
                    #pragma unroll
                    for(int d=0;d<DM;d++) acc += u[d]*w[j][d];
                    xzb[(rowbase+r)*XZW + tid + NTH*j] = acc*rm;
                }
            }
        }
        __syncthreads();   // own xz rows visible to own cvxp

        // ---- cvxp: needs halo rows from bid-1 ----
        if (seg_s > 0) wait_ge(&g_xz_ready[bid-1], (unsigned)(layer+1));
        {
            const int pair  = warp >> 1;
            const int split = warp & 1;
            const int r0    = pair*2;
            const int grow0 = rowbase + r0;
            const int l0    = grow0 % LP;
            const float* cwT = g_cwT + layer*4*ED;
            const float* Wx  = x_proj_w + layer*DBLW*ED;
            float part[2][DBLW];
            #pragma unroll
            for(int r=0;r<2;r++)
                #pragma unroll
                for(int t=0;t<DBLW;t++) part[r][t]=0.f;
            #pragma unroll
            for (int c=0;c<3;c++){
                int e0 = split*384 + c*128 + lane*4;
                float4 w0 = __ldg((const float4*)(cwT + 0*ED + e0));
                float4 w1 = __ldg((const float4*)(cwT + 1*ED + e0));
                float4 w2 = __ldg((const float4*)(cwT + 2*ED + e0));
                float4 b4 = __ldg((const float4*)(cwT + 3*ED + e0));
                float4 xm2 = {0,0,0,0}, xm1 = {0,0,0,0};
                if (l0>=2) xm2 = *(const float4*)(xzb + (grow0-2)*XZW + e0);
                if (l0>=1) xm1 = *(const float4*)(xzb + (grow0-1)*XZW + e0);
                float4 x0 = *(const float4*)(xzb + grow0*XZW + e0);
                float4 x1 = *(const float4*)(xzb + (grow0+1)*XZW + e0);
                float4 xc0, xc1;
                xc0.x = siluf_(b4.x + w0.x*xm2.x + w1.x*xm1.x + w2.x*x0.x);
                xc0.y = siluf_(b4.y + w0.y*xm2.y + w1.y*xm1.y + w2.y*x0.y);
                xc0.z = siluf_(b4.z + w0.z*xm2.z + w1.z*xm1.z + w2.z*x0.z);
                xc0.w = siluf_(b4.w + w0.w*xm2.w + w1.w*xm1.w + w2.w*x0.w);
                xc1.x = siluf_(b4.x + w0.x*xm1.x + w1.x*x0.x + w2.x*x1.x);
                xc1.y = siluf_(b4.y + w0.y*xm1.y + w1.y*x0.y + w2.y*x1.y);
                xc1.z = siluf_(b4.z + w0.z*xm1.z + w1.z*x0.z + w2.z*x1.z);
                xc1.w = siluf_(b4.w + w0.w*xm1.w + w1.w*x0.w + w2.w*x1.w);
                *(float4*)(sxc + r0*ED + e0)     = xc0;
                *(float4*)(sxc + (r0+1)*ED + e0) = xc1;
                #pragma unroll
                for(int t=0;t<DBLW;t++){
                    float4 wt = __ldg((const float4*)(Wx + t*ED + e0));
                    part[0][t] += wt.x*xc0.x + wt.y*xc0.y + wt.z*xc0.z + wt.w*xc0.w;
                    part[1][t] += wt.x*xc1.x + wt.y*xc1.y + wt.z*xc1.z + wt.w*xc1.w;
                }
            }
            #pragma unroll
            for(int r=0;r<2;r++)
                #pragma unroll
                for(int t=0;t<DBLW;t++){
                    float v = part[r][t];
                    for(int off=16;off>0;off>>=1) v += __shfl_down_sync(0xffffffffu, v, off);
                    if (lane==0) stmp[(split*SEGL + r0 + r)*DBLW + t] = v;
                }
        }
        __syncthreads();
        if (tid == 0){ __threadfence(); atomicAdd(&g_xz_ack[bid], 1u); }
        for (int idx = tid; idx < SEGL*DBLW; idx += NTH){
            int row = idx / DBLW, t = idx % DBLW;
            float v = stmp[row*DBLW + t] + stmp[(SEGL+row)*DBLW + t];
            sdb[row*DBLS + (t==0 ? 16 : (t-1))] = v;
        }
        __syncthreads();
        {
            float dw = dt_proj_w[layer*ED + tid];
            float db = dt_proj_b[layer*ED + tid];
            #pragma unroll 4
            for (int r=0;r<SEGL;r++){
                float d0 = sdb[r*DBLS + 16];
                sdl[r*ED + tid] = softplusf_(d0*dw + db);
            }
        }
        __syncthreads();

        // ---- chain scan: exact state handoff between segments ----
        int e = tid;
        float a2[NS];
        {
            const float* ap = g_A2 + (layer*ED + e)*NS;
            #pragma unroll
            for(int n=0;n<NS;n++) a2[n]=ap[n];
        }
        bool geo = true;
        #pragma unroll
        for(int n=1;n<NS;n++)
            geo = geo && (fabsf(a2[n] - (float)(n+1)*a2[0]) <= 1e-4f*fabsf(a2[n]));

        float hin[NS];
        if (seg_s > 0){
            wait_ge(&g_he_ready[bid-1], (unsigned)(layer+1));
            const float* hb = g_hend + (layer&1)*HENDSTRIDE + (bid-1)*NS*ED + e;
            #pragma unroll
            for(int n=0;n<NS;n++) hin[n] = hb[n*ED];
            __syncthreads();
            if (tid == 0){ __threadfence(); atomicAdd(&g_he_ack[bid-1], 1u); }
        } else {
            #pragma unroll
            for(int n=0;n<NS;n++) hin[n] = 0.f;
        }
        {
            float Dv = Dp[layer*ED + e];
            float st[NS];
            float a20 = a2[0];
            if (geo){
                ull st2[4] = {pk2_(hin[0],hin[1]), pk2_(hin[2],hin[3]),
                              pk2_(hin[4],hin[5]), pk2_(hin[6],hin[7])};
                float z_n = xzb[rowbase*XZW + ED + e];
                for (int li=0; li<SEGL; li++){
                    float z = z_n;
                    if (li < SEGL-1) z_n = xzb[(rowbase+li+1)*XZW + ED + e];
                    float delta = sdl[li*ED + e];
                    float xc    = sxc[li*ED + e];
                    float dx = delta * xc;
                    ulonglong2 Bp = *(const ulonglong2*)(sdb + li*DBLS);
                    ulonglong2 Bq = *(const ulonglong2*)(sdb + li*DBLS + 4);
                    ulonglong2 Cp = *(const ulonglong2*)(sdb + li*DBLS + 8);
                    ulonglong2 Cq = *(const ulonglong2*)(sdb + li*DBLS + 12);
                    float p  = ex2f_(delta * a20);
                    float p2 = p*p;
                    ull da01 = pk2_(p, p2);
                    ull p22  = pk2_(p2, p2);
                    ull da23 = mul2_(da01, p22);
                    ull da45 = mul2_(da23, p22);
                    ull da67 = mul2_(da45, p22);
                    ull dx2  = pk2_(dx, dx);
                    st2[0] = fma2_(da01, st2[0], mul2_(dx2, Bp.x));
                    st2[1] = fma2_(da23, st2[1], mul2_(dx2, Bp.y));
                    st2[2] = fma2_(da45, st2[2], mul2_(dx2, Bq.x));
                    st2[3] = fma2_(da67, st2[3], mul2_(dx2, Bq.y));
                    ull y2 = pk2_(Dv*xc, 0.f);
                    y2 = fma2_(st2[0], Cp.x, y2);
                    y2 = fma2_(st2[1], Cp.y, y2);
                    y2 = fma2_(st2[2], Cq.x, y2);
                    y2 = fma2_(st2[3], Cq.y, y2);
                    float ylo, yhi; upk2_(ylo, yhi, y2);
                    sxc[li*ED + e] = (ylo + yhi) * siluf_(z);
                }
                #pragma unroll
                for(int k=0;k<4;k++) upk2_(st[2*k], st[2*k+1], st2[k]);
            } else {
                #pragma unroll
                for(int n=0;n<NS;n++) st[n]=hin[n];
                float z_n = xzb[rowbase*XZW + ED + e];
                for (int li=0; li<SEGL; li++){
                    float z = z_n;
                    if (li < SEGL-1) z_n = xzb[(rowbase+li+1)*XZW + ED + e];
                    float delta = sdl[li*ED + e];
                    float xc    = sxc[li*ED + e];
                    float dx = delta * xc;
                    float4 B0 = *(const float4*)(sdb + li*DBLS);
                    float4 B1 = *(const float4*)(sdb + li*DBLS + 4);
                    float4 C0 = *(const float4*)(sdb + li*DBLS + 8);
                    float4 C1 = *(const float4*)(sdb + li*DBLS + 12);
                    float Bv[NS] = {B0.x,B0.y,B0.z,B0.w,B1.x,B1.y,B1.z,B1.w};
                    float Cv[NS] = {C0.x,C0.y,C0.z,C0.w,C1.x,C1.y,C1.z,C1.w};
                    float y = Dv * xc;
                    #pragma unroll
                    for(int n=0;n<NS;n++){
                        float dan = ex2f_(delta * a2[n]);
                        st[n] = dan*st[n] + dx*Bv[n];
                        y += st[n]*Cv[n];
                    }
                    sxc[li*ED + e] = y * siluf_(z);
                }
            }
            if (seg_s < NSEG-1){
                if (layer >= 2) wait_ge(&g_he_ack[bid], (unsigned)(layer-1));
                float* hb = g_hend + (layer&1)*HENDSTRIDE + bid*NS*ED + e;
                #pragma unroll
                for(int n=0;n<NS;n++) hb[n*ED] = st[n];
                signal_release(&g_he_ready[bid]);   // = layer+1
            }
        }
        __syncthreads();

        // ---- out_proj (residual update in smem) ----
        {
            const int pair  = warp >> 1;
            const int split = warp & 1;
            const int r0    = pair*2;
            const float* Wo = out_proj_w + layer*DM*ED;
            float pd[2][DM];
            #pragma unroll
            for(int r=0;r<2;r++)
                #pragma unroll
                for(int d=0;d<DM;d++) pd[r][d]=0.f;
            #pragma unroll
            for (int c=0;c<3;c++){
                int e0 = split*384 + c*128 + lane*4;
                float4 y0 = *(const float4*)(sxc + r0*ED + e0);
                float4 y1 = *(const float4*)(sxc + (r0+1)*ED + e0);
                #pragma unroll
                for(int d=0;d<DM;d++){
                    float4 wd4 = __ldg((const float4*)(Wo + d*ED + e0));
                    pd[0][d] += wd4.x*y0.x + wd4.y*y0.y + wd4.z*y0.z + wd4.w*y0.w;
                    pd[1][d] += wd4.x*y1.x + wd4.y*y1.y + wd4.z*y1.z + wd4.w*y1.w;
                }
            }
            #pragma unroll
            for(int r=0;r<2;r++)
                #pragma unroll
                for(int d=0;d<DM;d++){
                    float v = pd[r][d];
                    for(int off=16;off>0;off>>=1) v += __shfl_down_sync(0xffffffffu, v, off);
                    if (lane==0) stmp[(split*SEGL + r0 + r)*DM + d] = v;
                }
        }
        __syncthreads();
        if (tid < SEGL*DM)
            sres[tid] += stmp[tid] + stmp[SEGL*DM + tid];
        __syncthreads();
    }

    // write residual back for the final phase
    if (tid < SEGL*DM) g_h[rowbase*DM + tid] = sres[tid];
    gridbar();

    // ===== final: mean over L + FC + ReLU =====
    {
        float* m = sm;
        for (int b = bid; b < BSZ; b += NB){
            if (tid < DM){
                float s=0.f;
                for(int l=0;l<LP;l++) s += g_h[(b*LP+l)*DM + tid];
                m[tid]=s*(1.0f/LP);
            }
            __syncthreads();
            if (tid < EMB){
                float acc = fc_b[tid];
                #pragma unroll
                for(int d=0;d<DM;d++) acc += m[d]*fc_w[tid*DM+d];
                out[b*EMB+tid] = fmaxf(acc,0.0f);
            }
            __syncthreads();
        }
    }
}

// ---------------- launch ----------------
extern "C" void kernel_launch(void* const* d_in, const int* in_sizes, int n_in,
                              void* d_out, int out_size){
    const float* x          = (const float*)d_in[0];
    const float* conv_re_w  = (const float*)d_in[1];
    const float* conv_re_b  = (const float*)d_in[2];
    const float* conv_im_w  = (const float*)d_in[3];
    const float* conv_im_b  = (const float*)d_in[4];
    const float* pos        = (const float*)d_in[5];
    const float* bn_gamma   = (const float*)d_in[6];
    const float* bn_beta    = (const float*)d_in[7];
    const float* rms_w      = (const float*)d_in[8];
    const float* in_proj_w  = (const float*)d_in[9];
    const float* conv1d_w   = (const float*)d_in[10];
    const float* conv1d_b   = (const float*)d_in[11];
    const float* x_proj_w   = (const float*)d_in[12];
    const float* dt_proj_w  = (const float*)d_in[13];
    const float* dt_proj_b  = (const float*)d_in[14];
    const float* A_log      = (const float*)d_in[15];
    const float* Dp         = (const float*)d_in[16];
    const float* out_proj_w = (const float*)d_in[17];
    const float* fc_w       = (const float*)d_in[18];
    const float* fc_b       = (const float*)d_in[19];
    float* out = (float*)d_out;

    size_t dynbytes = (size_t)DYNF * sizeof(float);
    cudaFuncSetAttribute(k_mega, cudaFuncAttributeMaxDynamicSharedMemorySize, (int)dynbytes);

    k_mega<<<NBLK, NTH, dynbytes>>>(x, conv_re_w, conv_re_b, conv_im_w, conv_im_b, pos,
                         bn_gamma, bn_beta, rms_w, in_proj_w, conv1d_w, conv1d_b,
                         x_proj_w, dt_proj_w, dt_proj_b, A_log, Dp, out_proj_w,
                         fc_w, fc_b, out);
}